// round 12
// baseline (speedup 1.0000x reference)
#include <cuda_runtime.h>

#define NN 8
#define CIN 256
#define LTOT 3136
#define CH 128
#define GG 8
#define HH 56
#define NB 448          // NN*56
#define QC 256
#define RELW 111
#define INV25088 (1.f / 25088.f)

// ---------------- device scratch (static, no allocation) ----------------
__device__ float g_featA[NN * CH * LTOT];   // 12.8 MB
__device__ float g_featB[NN * CH * LTOT];   // 12.8 MB
__device__ float g_qkv[NB * QC * HH];       // 25.7 MB (reused for conv_up out)
__device__ float g_so[NB * QC * HH];        // 25.7 MB
__device__ float g_stats[4992];             // all BN stat accumulators (see offsets)
__device__ float g_SU[3][2][8][56];         // sliding sums of rel_q / rel_k per axial
__device__ float g_U[3][2][56][64];         // sliding pair-product sums, i-MAJOR (coalesced)

// offsets into g_stats
#define OFF_BN1 0            // 2*128
#define OFF_BNQ 256          // 3 * 512
#define OFF_SIM 1792         // 3 * 8 replicas * 48
#define OFF_BNO 2944         // 3 * 512
#define OFF_BN2 4480         // 2*256
#define STATS_TOTAL 4992

// ---------------- helpers ----------------
__device__ __forceinline__ float fast_exp(float x) {
    float y = x * 1.4426950408889634f;
    y = fmaxf(y, -120.0f);
    float n = floorf(y);
    float f = y - n;
    float p = 1.8775767e-3f;
    p = fmaf(p, f, 8.9893397e-3f);
    p = fmaf(p, f, 5.5826318e-2f);
    p = fmaf(p, f, 2.4015361e-1f);
    p = fmaf(p, f, 6.9315308e-1f);
    p = fmaf(p, f, 9.9999994e-1f);
    return p * __int_as_float(((int)n + 127) << 23);
}

// packed f32x2 ops (Blackwell FFMA2 — PTX-only pattern)
__device__ __forceinline__ unsigned long long f2pack(float lo, float hi) {
    unsigned long long r;
    asm("mov.b64 %0, {%1, %2};" : "=l"(r) : "f"(lo), "f"(hi));
    return r;
}
__device__ __forceinline__ void f2fma(unsigned long long& d, unsigned long long a,
                                      unsigned long long b) {
    asm("fma.rn.f32x2 %0, %1, %2, %0;" : "+l"(d) : "l"(a), "l"(b));
}
__device__ __forceinline__ unsigned long long f2mul(unsigned long long a,
                                                    unsigned long long b) {
    unsigned long long r;
    asm("mul.rn.f32x2 %0, %1, %2;" : "=l"(r) : "l"(a), "l"(b));
    return r;
}
__device__ __forceinline__ float2 f2unpack(unsigned long long v) {
    float2 r;
    asm("mov.b64 {%0, %1}, %2;" : "=f"(r.x), "=f"(r.y) : "l"(v));
    return r;
}

// ---------------- init: parallel rel tables (all 3 axials) + zero stats ------
__global__ void k_init(const float* __restrict__ rel) {
    int bid = blockIdx.x;
    int t = threadIdx.x;
    if (bid < 24) {
        int a = bid >> 3;
        const float* rb = rel + a * 32 * RELW;
        int w = (bid & 7) * 256 + t;   // 0..2047
#pragma unroll
        for (int rep = 0; rep < 4; rep++, w += 2048) {
            if (w < 7168) {
                int s = w / 3584;
                int r = w - s * 3584;
                int P = r / 56, i = r % 56;
                int c = P >> 3, cp = P & 7;
                const float* r1 = rb + (s * 8 + c) * RELW + i;
                const float* r2 = rb + (s * 8 + cp) * RELW + i;
                float u = 0.f;
#pragma unroll
                for (int d = 0; d < 56; d++) u = fmaf(r1[d], r2[d], u);
                g_U[a][s][i][P] = u;
            } else if (w < 8064) {
                int w2 = w - 7168;
                int s = w2 / 448;
                int r = w2 - s * 448;
                int c = r / 56, i = r % 56;
                const float* rr = rb + (s * 8 + c) * RELW + i;
                float u = 0.f;
#pragma unroll
                for (int d = 0; d < 56; d++) u += rr[d];
                g_SU[a][s][c][i] = u;
            }
        }
    } else {
        for (int i = (bid - 24) * 256 + t; i < STATS_TOTAL; i += 4 * 256)
            g_stats[i] = 0.f;
    }
}

// ---------------- grouped conv down + fused bn1 stats ----------------
__global__ __launch_bounds__(224) void k_conv_down(const float* __restrict__ x,
                                                   const float* __restrict__ w,
                                                   float* __restrict__ out,
                                                   float* __restrict__ statOut) {
    __shared__ float sW[16][32];
    __shared__ float sRs[7][16], sRq[7][16];
    int lt = blockIdx.x % 14;
    int g  = (blockIdx.x / 14) % GG;
    int n  = blockIdx.x / (14 * GG);
    int t = threadIdx.x;
    for (int i = t; i < 512; i += 224) sW[i >> 5][i & 31] = w[(g * 16) * 32 + i];
    __syncthreads();
    int l = lt * 224 + t;
    float acc[16];
#pragma unroll
    for (int o = 0; o < 16; o++) acc[o] = 0.f;
    const float* xp = x + ((size_t)(n * CIN + g * 32)) * LTOT + l;
#pragma unroll 8
    for (int k = 0; k < 32; k++) {
        float xv = xp[(size_t)k * LTOT];
#pragma unroll
        for (int o = 0; o < 16; o++) acc[o] = fmaf(sW[o][k], xv, acc[o]);
    }
    float* op = out + ((size_t)(n * CH + g * 16)) * LTOT + l;
#pragma unroll
    for (int o = 0; o < 16; o++) op[(size_t)o * LTOT] = acc[o];
    int lane = t & 31, wp = t >> 5;
#pragma unroll
    for (int o = 0; o < 16; o++) {
        float v = acc[o], v2 = v * v;
#pragma unroll
        for (int off = 16; off; off >>= 1) {
            v += __shfl_xor_sync(~0u, v, off);
            v2 += __shfl_xor_sync(~0u, v2, off);
        }
        if (lane == 0) { sRs[wp][o] = v; sRq[wp][o] = v2; }
    }
    __syncthreads();
    if (t < 16) {
        float a1 = 0.f, a2 = 0.f;
#pragma unroll
        for (int w2 = 0; w2 < 7; w2++) { a1 += sRs[w2][t]; a2 += sRq[w2][t]; }
        atomicAdd(&statOut[(g * 16 + t) * 2], a1);
        atomicAdd(&statOut[(g * 16 + t) * 2 + 1], a2);
    }
}

// ---------------- QKV GEMM per b-row + inline bn1 coef + fused bn_qkv stats --
// R8 structure (256 thr, 8x7 tile) with f32x2-packed accumulators.
template <int PROX, int USEBN>
__global__ __launch_bounds__(256) void k_qkv(const float* __restrict__ src,
                                             const float* __restrict__ W,
                                             float* __restrict__ qkv,
                                             const float* __restrict__ inStat,
                                             const float* __restrict__ gam,
                                             const float* __restrict__ bet,
                                             float* __restrict__ statOut) {
    __shared__ float sX[128][57];      // 29184 B; reused: stats scratch + out staging
    __shared__ float sW4[256][12];     // 12288 B; coef scratch before first fill
    int b = blockIdx.x;
    int n = b / HH, wpos = b % HH;
    int t = threadIdx.x;
    float* sCA = &sW4[0][0];
    float* sCB = sCA + 128;
    if (USEBN) {
        if (t < 128) {
            float m = inStat[2 * t] * INV25088;
            float var = inStat[2 * t + 1] * INV25088 - m * m;
            float a = gam[t] * rsqrtf(var + 1e-5f);
            sCA[t] = a; sCB[t] = bet[t] - m * a;
        }
        __syncthreads();
    }
    for (int i = t; i < CH * HH; i += 256) {
        int c = i / HH, h = i - c * HH;
        size_t idx = PROX ? (((size_t)(n * CH + c) * HH + wpos) * HH + h)
                          : (((size_t)(n * CH + c) * HH + h) * HH + wpos);
        float v = src[idx];
        if (USEBN) { v = fmaf(v, sCA[c], sCB[c]); v = fmaxf(v, 0.f); }
        sX[c][h] = v;
    }
    int o0 = t & 31;
    int h0 = (t >> 5) * 7;
    unsigned long long acc01[8], acc23[8], acc45[8];
    float acc6[8];
#pragma unroll
    for (int m = 0; m < 8; m++) {
        acc01[m] = 0ull; acc23[m] = 0ull; acc45[m] = 0ull; acc6[m] = 0.f;
    }

    for (int cc = 0; cc < 128; cc += 8) {
        __syncthreads();
        for (int i = t; i < 2048; i += 256)
            sW4[i >> 3][i & 7] = W[(i >> 3) * 128 + cc + (i & 7)];
        __syncthreads();
#pragma unroll
        for (int j4 = 0; j4 < 2; j4++) {
            float4 w4[8];
#pragma unroll
            for (int m = 0; m < 8; m++)
                w4[m] = *(const float4*)&sW4[o0 + 32 * m][j4 * 4];
#pragma unroll
            for (int jj = 0; jj < 4; jj++) {
                int c = cc + j4 * 4 + jj;
                float xv[7];
#pragma unroll
                for (int u = 0; u < 7; u++) xv[u] = sX[c][h0 + u];
                unsigned long long x01 = f2pack(xv[0], xv[1]);
                unsigned long long x23 = f2pack(xv[2], xv[3]);
                unsigned long long x45 = f2pack(xv[4], xv[5]);
#pragma unroll
                for (int m = 0; m < 8; m++) {
                    float wv = (jj == 0) ? w4[m].x : (jj == 1) ? w4[m].y
                             : (jj == 2) ? w4[m].z : w4[m].w;
                    unsigned long long w2 = f2pack(wv, wv);
                    f2fma(acc01[m], w2, x01);
                    f2fma(acc23[m], w2, x23);
                    f2fma(acc45[m], w2, x45);
                    acc6[m] = fmaf(wv, xv[6], acc6[m]);
                }
            }
        }
    }
    // unpack accumulators
    float acc[8][7];
#pragma unroll
    for (int m = 0; m < 8; m++) {
        float2 a0 = f2unpack(acc01[m]);
        float2 a1 = f2unpack(acc23[m]);
        float2 a2 = f2unpack(acc45[m]);
        acc[m][0] = a0.x; acc[m][1] = a0.y;
        acc[m][2] = a1.x; acc[m][3] = a1.y;
        acc[m][4] = a2.x; acc[m][5] = a2.y;
        acc[m][6] = acc6[m];
    }
    // ---- fused stats (scratch = sX region, inputs no longer needed) ----
    __syncthreads();
    {
        float* scr = &sX[0][0];
        int wp = t >> 5;
#pragma unroll
        for (int m = 0; m < 8; m++) {
            float s = 0.f, qq = 0.f;
#pragma unroll
            for (int u = 0; u < 7; u++) { float v = acc[m][u]; s += v; qq = fmaf(v, v, qq); }
            scr[wp * 256 + o0 + 32 * m] = s;
            scr[2048 + wp * 256 + o0 + 32 * m] = qq;
        }
        __syncthreads();
        float a1 = 0.f, a2 = 0.f;
#pragma unroll
        for (int w2 = 0; w2 < 8; w2++) {
            a1 += scr[w2 * 256 + t];
            a2 += scr[2048 + w2 * 256 + t];
        }
        atomicAdd(&statOut[2 * t], a1);
        atomicAdd(&statOut[2 * t + 1], a2);
    }
    // ---- stage output through smem for coalesced global writes ----
    float* sOut = &sX[0][0];
#pragma unroll
    for (int half = 0; half < 2; half++) {
        __syncthreads();
#pragma unroll
        for (int m = 0; m < 4; m++) {
            int mm = m + 4 * half;
            int orow = o0 + 32 * m;
#pragma unroll
            for (int u = 0; u < 7; u++) sOut[orow * 57 + h0 + u] = acc[mm][u];
        }
        __syncthreads();
        float* dst = qkv + (size_t)b * (QC * HH) + half * 128 * HH;
        for (int i = t; i < 128 * HH; i += 256) {
            int o = i / HH, h = i - o * HH;
            dst[i] = sOut[o * 57 + h];
        }
    }
}

// ---------------- algebraic sim BN stats + inline bnq coef ------------------
__global__ __launch_bounds__(256) void k_simstats2(const float* __restrict__ qkv, int axial,
                                                   const float* __restrict__ bnqStat,
                                                   const float* __restrict__ gam,
                                                   const float* __restrict__ bet,
                                                   float* __restrict__ simOut) {
    __shared__ float sD[128][57];
    __shared__ float sCA[256], sCB[256];
    int b = blockIdx.x;
    int t = threadIdx.x;
    {
        float m = bnqStat[2 * t] * INV25088;
        float var = bnqStat[2 * t + 1] * INV25088 - m * m;
        float a = gam[t] * rsqrtf(var + 1e-5f);
        sCA[t] = a; sCB[t] = bet[t] - m * a;
    }
    __syncthreads();
    const float* base = qkv + (size_t)b * (QC * HH);
    for (int i = t; i < 128 * HH; i += 256) {
        int lc = i / HH, h = i - lc * HH;
        int g = lc >> 4, c = lc & 15;
        int o = g * 32 + c;
        sD[lc][h] = fmaf(base[o * HH + h], sCA[o], sCB[o]);
    }
    __syncthreads();
    int g = t >> 5, lane = t & 31;
    float accG[4], accW[4];
#pragma unroll
    for (int jj = 0; jj < 4; jj++) {
        int s = jj >> 1;
        int P = lane + 32 * (jj & 1);
        int c = P >> 3, cp = P & 7;
        const float* x1 = &sD[g * 16 + s * 8 + c][0];
        const float* x2 = &sD[g * 16 + s * 8 + cp][0];
        const float* U = &g_U[axial][s][0][P];   // i-major: stride 64 per i, lanes coalesced
        float gg = 0.f, ww = 0.f;
#pragma unroll
        for (int i = 0; i < 56; i++) {
            float p = x1[i] * x2[i];
            gg += p;
            ww = fmaf(p, __ldg(U + i * 64), ww);
        }
        accG[jj] = gg; accW[jj] = ww;
    }
    float pqk = 0.f, pqr = 0.f, pkr = 0.f;
    if (lane < 8) {
        const float* xq = &sD[g * 16 + lane][0];
        const float* xk = &sD[g * 16 + 8 + lane][0];
        float sq = 0.f, sk = 0.f, vq = 0.f, vk = 0.f;
#pragma unroll
        for (int i = 0; i < 56; i++) {
            sq += xq[i]; sk += xk[i];
            vq = fmaf(xq[i], __ldg(&g_SU[axial][0][lane][i]), vq);
            vk = fmaf(xk[i], __ldg(&g_SU[axial][1][lane][i]), vk);
        }
        pqk = sq * sk; pqr = vq; pkr = vk;
    }
    float ssqk = accG[0] * accG[2] + accG[1] * accG[3];
    float ssqr = accW[0] + accW[1];
    float sskr = accW[2] + accW[3];
#pragma unroll
    for (int off = 16; off; off >>= 1) {
        pqk += __shfl_xor_sync(~0u, pqk, off);
        pqr += __shfl_xor_sync(~0u, pqr, off);
        pkr += __shfl_xor_sync(~0u, pkr, off);
        ssqk += __shfl_xor_sync(~0u, ssqk, off);
        ssqr += __shfl_xor_sync(~0u, ssqr, off);
        sskr += __shfl_xor_sync(~0u, sskr, off);
    }
    if (lane == 0) {
        float* st = simOut + (b & 7) * 48;
        atomicAdd(&st[(0 * 8 + g) * 2 + 0], pqk);
        atomicAdd(&st[(0 * 8 + g) * 2 + 1], ssqk);
        atomicAdd(&st[(1 * 8 + g) * 2 + 0], pqr);
        atomicAdd(&st[(1 * 8 + g) * 2 + 1], ssqr);
        atomicAdd(&st[(2 * 8 + g) * 2 + 0], pkr);
        atomicAdd(&st[(2 * 8 + g) * 2 + 1], sskr);
    }
}

// ---------------- fused attention: f32x2 phase-2 with c-minor tables ---------
__global__ __launch_bounds__(224) void k_attn(const float* __restrict__ qkv,
                                              const float* __restrict__ rel,
                                              float* __restrict__ so,
                                              const float* __restrict__ bnqStat,
                                              const float* __restrict__ bqg,
                                              const float* __restrict__ bqb,
                                              const float* __restrict__ simStat,
                                              const float* __restrict__ bsg,
                                              const float* __restrict__ bsb,
                                              float* __restrict__ statOut) {
    __shared__ float sQ[8][57];
    __shared__ __align__(8)  float sKt[56][10];     // [j][c]
    __shared__ __align__(16) float sVt[56][20];     // [h][c]
    __shared__ __align__(8)  float sQEt[112][14];   // [d1][c] = QE[c][d1]
    __shared__ __align__(8)  float sKEt[112][14];   // [d1][c] = KE[c][110-d1]
    __shared__ __align__(16) float sVEt[112][20];   // [d][c]
    __shared__ float sSim[56][57];
    __shared__ float sInv[56];
    __shared__ float sCA[32], sCB[32], sP[6];
    int g = blockIdx.x & 7;
    int b = blockIdx.x >> 3;
    int t = threadIdx.x;
    if (t < 32) {
        int o = g * 32 + t;
        float m = bnqStat[2 * o] * INV25088;
        float var = bnqStat[2 * o + 1] * INV25088 - m * m;
        float a = bqg[o] * rsqrtf(var + 1e-5f);
        sCA[t] = a; sCB[t] = bqb[o] - m * a;
    } else if (t < 35) {
        int p = t - 32;
        int ch = p * 8 + g;
        float s1 = 0.f, s2 = 0.f;
#pragma unroll
        for (int r = 0; r < 8; r++) { s1 += simStat[r * 48 + ch * 2]; s2 += simStat[r * 48 + ch * 2 + 1]; }
        const float invc = 1.f / (448.f * 3136.f);
        float m = s1 * invc;
        float var = s2 * invc - m * m;
        float a = bsg[ch] * rsqrtf(var + 1e-5f);
        sP[p] = a; sP[3 + p] = bsb[ch] - m * a;
    }
    __syncthreads();
    const float* base = qkv + (size_t)b * (QC * HH) + g * 32 * HH;
    for (int i = t; i < 32 * HH; i += 224) {
        int c = i / HH, h = i - c * HH;
        float v = fmaf(base[c * HH + h], sCA[c], sCB[c]);
        if (c < 8) sQ[c][h] = v;
        else if (c < 16) sKt[h][c - 8] = v;
        else sVt[h][c - 16] = v;
    }
    for (int i = t; i < 8 * 111; i += 224) {
        int c = i / 111, d = i - c * 111;
        sQEt[d][c] = rel[c * RELW + d];
        sKEt[d][c] = rel[(8 + c) * RELW + (110 - d)];
    }
    for (int i = t; i < 16 * 111; i += 224) {
        int c = i / 111, d = i - c * 111;
        sVEt[d][c] = rel[(16 + c) * RELW + d];
    }
    __syncthreads();
    float aqk = sP[0], aqr = sP[1], akr = sP[2];
    float bias = sP[3] + sP[4] + sP[5];
    int i0 = t >> 2, jt = t & 3;
    unsigned long long qp[4];
#pragma unroll
    for (int a = 0; a < 4; a++) qp[a] = f2pack(sQ[2 * a][i0], sQ[2 * a + 1][i0]);
    unsigned long long aqk2 = f2pack(aqk, aqk);
    unsigned long long aqr2 = f2pack(aqr, aqr);
    unsigned long long akr2 = f2pack(akr, akr);
    unsigned long long bias2 = f2pack(bias, 0.f);
    float lg[14];
#pragma unroll
    for (int u = 0; u < 14; u++) {
        int j = jt * 14 + u;
        int d1 = i0 - j + 55;
        const unsigned long long* kp = (const unsigned long long*)&sKt[j][0];
        const unsigned long long* qe = (const unsigned long long*)&sQEt[d1][0];
        const unsigned long long* ke = (const unsigned long long*)&sKEt[d1][0];
        unsigned long long kk0 = kp[0], kk1 = kp[1], kk2 = kp[2], kk3 = kp[3];
        unsigned long long qk2 = f2mul(qp[0], kk0);
        f2fma(qk2, qp[1], kk1); f2fma(qk2, qp[2], kk2); f2fma(qk2, qp[3], kk3);
        unsigned long long qr2 = f2mul(qp[0], qe[0]);
        f2fma(qr2, qp[1], qe[1]); f2fma(qr2, qp[2], qe[2]); f2fma(qr2, qp[3], qe[3]);
        unsigned long long kr2 = f2mul(kk0, ke[0]);
        f2fma(kr2, kk1, ke[1]); f2fma(kr2, kk2, ke[2]); f2fma(kr2, kk3, ke[3]);
        unsigned long long lg2 = bias2;
        f2fma(lg2, aqk2, qk2);
        f2fma(lg2, aqr2, qr2);
        f2fma(lg2, akr2, kr2);
        float2 L = f2unpack(lg2);
        lg[u] = L.x + L.y;
    }
    float m = -1e30f;
#pragma unroll
    for (int u = 0; u < 14; u++) m = fmaxf(m, lg[u]);
    m = fmaxf(m, __shfl_xor_sync(~0u, m, 1));
    m = fmaxf(m, __shfl_xor_sync(~0u, m, 2));
    float s = 0.f;
#pragma unroll
    for (int u = 0; u < 14; u++) { lg[u] = fast_exp(lg[u] - m); s += lg[u]; }
    s += __shfl_xor_sync(~0u, s, 1);
    s += __shfl_xor_sync(~0u, s, 2);
#pragma unroll
    for (int u = 0; u < 14; u++) sSim[i0][jt * 14 + u] = lg[u];
    if (jt == 0) sInv[i0] = 1.f / s;
    __syncthreads();
    int c4 = t / 56, ii = t % 56;
    unsigned long long a01 = 0ull, a23 = 0ull, e01 = 0ull, e23 = 0ull;
#pragma unroll 4
    for (int j = 0; j < 56; j++) {
        float e = sSim[ii][j];
        unsigned long long ee = f2pack(e, e);
        ulonglong2 v2 = *(const ulonglong2*)&sVt[j][c4 * 4];
        ulonglong2 ve2 = *(const ulonglong2*)&sVEt[ii - j + 55][c4 * 4];
        f2fma(a01, ee, v2.x);
        f2fma(a23, ee, v2.y);
        f2fma(e01, ee, ve2.x);
        f2fma(e23, ee, ve2.y);
    }
    float inv = sInv[ii];
    float2 ua = f2unpack(a01), ub = f2unpack(a23);
    float2 uc = f2unpack(e01), ud = f2unpack(e23);
    float vals[8];
    vals[0] = ua.x * inv; vals[1] = uc.x * inv;
    vals[2] = ua.y * inv; vals[3] = uc.y * inv;
    vals[4] = ub.x * inv; vals[5] = ud.x * inv;
    vals[6] = ub.y * inv; vals[7] = ud.y * inv;
    float* ob = so + (size_t)b * (QC * HH) + (g * 32) * HH + ii;
#pragma unroll
    for (int z = 0; z < 4; z++) {
        int c = c4 * 4 + z;
        ob[(2 * c) * HH] = vals[z * 2 + 0];
        ob[(2 * c + 1) * HH] = vals[z * 2 + 1];
    }
    __syncthreads();
    {
        float* sRed = &sSim[0][0];
#pragma unroll
        for (int z = 0; z < 4; z++) {
            sRed[t * 8 + z * 2 + 0] = vals[z * 2 + 0];
            sRed[t * 8 + z * 2 + 1] = vals[z * 2 + 1];
        }
        __syncthreads();
        if (t < 32) {
            int c4r = t >> 3, z = (t >> 1) & 3, p = t & 1;
            int off = z * 2 + p;
            float a1 = 0.f, a2 = 0.f;
            for (int ii2 = 0; ii2 < 56; ii2++) {
                float v = sRed[(c4r * 56 + ii2) * 8 + off];
                a1 += v; a2 = fmaf(v, v, a2);
            }
            atomicAdd(&statOut[2 * (g * 32 + t)], a1);
            atomicAdd(&statOut[2 * (g * 32 + t) + 1], a2);
        }
    }
}

// ---------------- bn_out apply + pair sum, prox=1 (inline coef) -------------
__global__ __launch_bounds__(256) void k_recombine(const float* __restrict__ so,
                                                   float* __restrict__ dst,
                                                   const float* __restrict__ st,
                                                   const float* __restrict__ bog,
                                                   const float* __restrict__ bob) {
    int idx = blockIdx.x * 256 + threadIdx.x;
    if (idx >= NB * CH * HH) return;
    int h = idx % HH;
    int cc = (idx / HH) % CH;
    int row = idx / (HH * CH);
    int o = 2 * cc;
    float m0 = st[2 * o] * INV25088;
    float v0 = st[2 * o + 1] * INV25088 - m0 * m0;
    float a0 = bog[o] * rsqrtf(v0 + 1e-5f);
    float b0 = bob[o] - m0 * a0;
    float m1 = st[2 * o + 2] * INV25088;
    float v1 = st[2 * o + 3] * INV25088 - m1 * m1;
    float a1 = bog[o + 1] * rsqrtf(v1 + 1e-5f);
    float b1 = bob[o + 1] - m1 * a1;
    float v = fmaf(so[(size_t)row * (QC * HH) + o * HH + h], a0, b0) +
              fmaf(so[(size_t)row * (QC * HH) + (o + 1) * HH + h], a1, b1);
    int n = row / HH, wpos = row % HH;
    dst[((size_t)(n * CH + cc) * HH + wpos) * HH + h] = v;
}

// ---------------- bn_out apply + pair sum, prox=0 (smem transpose) ----------
__global__ __launch_bounds__(256) void k_recombine_t(const float* __restrict__ so,
                                                     float* __restrict__ dst,
                                                     const float* __restrict__ st,
                                                     const float* __restrict__ bog,
                                                     const float* __restrict__ bob) {
    __shared__ float sT[56][57];
    int cc = blockIdx.x & 127;
    int n = blockIdx.x >> 7;
    int t = threadIdx.x;
    int o = 2 * cc;
    float m0 = st[2 * o] * INV25088;
    float v0 = st[2 * o + 1] * INV25088 - m0 * m0;
    float a0 = bog[o] * rsqrtf(v0 + 1e-5f);
    float b0 = bob[o] - m0 * a0;
    float m1 = st[2 * o + 2] * INV25088;
    float v1 = st[2 * o + 3] * INV25088 - m1 * m1;
    float a1 = bog[o + 1] * rsqrtf(v1 + 1e-5f);
    float b1 = bob[o + 1] - m1 * a1;
    const float* base = so + ((size_t)n * HH) * (QC * HH);
    for (int i = t; i < 56 * 56; i += 256) {
        int w = i / 56, h = i - w * 56;
        const float* r = base + (size_t)w * (QC * HH) + o * HH + h;
        sT[w][h] = fmaf(r[0], a0, b0) + fmaf(r[HH], a1, b1);
    }
    __syncthreads();
    float* d = dst + ((size_t)(n * CH + cc)) * LTOT;
    for (int i = t; i < 56 * 56; i += 256) {
        int a = i / 56, bb = i - a * 56;
        d[i] = sT[bb][a];
    }
}

// ---------------- grouped conv up + fused bn2 stats -----------------------
__global__ __launch_bounds__(224) void k_conv_up(const float* __restrict__ hbuf,
                                                 const float* __restrict__ w,
                                                 float* __restrict__ out,
                                                 float* __restrict__ statOut) {
    __shared__ float sW[32][16];
    __shared__ float sRs[7][32], sRq[7][32];
    int lt = blockIdx.x % 14;
    int g  = (blockIdx.x / 14) % GG;
    int n  = blockIdx.x / (14 * GG);
    int t = threadIdx.x;
    for (int i = t; i < 512; i += 224) sW[i >> 4][i & 15] = w[(g * 32) * 16 + i];
    __syncthreads();
    int l = lt * 224 + t;
    float acc[32];
#pragma unroll
    for (int o = 0; o < 32; o++) acc[o] = 0.f;
    const float* hp = hbuf + ((size_t)(n * CH + g * 16)) * LTOT + l;
#pragma unroll 4
    for (int k = 0; k < 16; k++) {
        float hv = fmaxf(hp[(size_t)k * LTOT], 0.f);
#pragma unroll
        for (int o = 0; o < 32; o++) acc[o] = fmaf(sW[o][k], hv, acc[o]);
    }
    float* op = out + ((size_t)(n * CIN + g * 32)) * LTOT + l;
#pragma unroll
    for (int o = 0; o < 32; o++) op[(size_t)o * LTOT] = acc[o];
    int lane = t & 31, wp = t >> 5;
#pragma unroll
    for (int o = 0; o < 32; o++) {
        float v = acc[o], v2 = v * v;
#pragma unroll
        for (int off = 16; off; off >>= 1) {
            v += __shfl_xor_sync(~0u, v, off);
            v2 += __shfl_xor_sync(~0u, v2, off);
        }
        if (lane == 0) { sRs[wp][o] = v; sRq[wp][o] = v2; }
    }
    __syncthreads();
    if (t < 32) {
        float a1 = 0.f, a2 = 0.f;
#pragma unroll
        for (int w2 = 0; w2 < 7; w2++) { a1 += sRs[w2][t]; a2 += sRq[w2][t]; }
        atomicAdd(&statOut[(g * 32 + t) * 2], a1);
        atomicAdd(&statOut[(g * 32 + t) * 2 + 1], a2);
    }
}

// ---------------- final: relu(x + bn2(conv_up) * rw), float4, inline coef ----
__global__ __launch_bounds__(256) void k_final(const float4* __restrict__ x,
                                               const float4* __restrict__ cu,
                                               const float* __restrict__ rw,
                                               float4* __restrict__ out,
                                               const float* __restrict__ st,
                                               const float* __restrict__ g2,
                                               const float* __restrict__ b2) {
    int idx = blockIdx.x * 256 + threadIdx.x;
    if (idx >= NN * CIN * (LTOT / 4)) return;
    int ch = (idx / (LTOT / 4)) & 255;
    float m = st[2 * ch] * INV25088;
    float var = st[2 * ch + 1] * INV25088 - m * m;
    float a = g2[ch] * rsqrtf(var + 1e-5f);
    float bb = b2[ch] - m * a;
    float wv = __ldg(rw);
    float4 c = cu[idx], xx = x[idx], r;
    r.x = fmaxf(fmaf(fmaf(c.x, a, bb), wv, xx.x), 0.f);
    r.y = fmaxf(fmaf(fmaf(c.y, a, bb), wv, xx.y), 0.f);
    r.z = fmaxf(fmaf(fmaf(c.z, a, bb), wv, xx.z), 0.f);
    r.w = fmaxf(fmaf(fmaf(c.w, a, bb), wv, xx.w), 0.f);
    out[idx] = r;
}

// ---------------- launch ----------------
extern "C" void kernel_launch(void* const* d_in, const int* in_sizes, int n_in,
                              void* d_out, int out_size) {
    const float* x    = (const float*)d_in[0];
    const float* cdw  = (const float*)d_in[1];
    const float* bn1g = (const float*)d_in[2];
    const float* bn1b = (const float*)d_in[3];
    const float* qkvw = (const float*)d_in[4];
    const float* bqg  = (const float*)d_in[5];
    const float* bqb  = (const float*)d_in[6];
    const float* bsg  = (const float*)d_in[7];
    const float* bsb  = (const float*)d_in[8];
    const float* bog  = (const float*)d_in[9];
    const float* bob  = (const float*)d_in[10];
    const float* rel  = (const float*)d_in[11];
    const float* cuw  = (const float*)d_in[12];
    const float* bn2g = (const float*)d_in[13];
    const float* bn2b = (const float*)d_in[14];
    const float* rw   = (const float*)d_in[15];
    float* out = (float*)d_out;

    float *fA, *fB, *qk, *so, *gs;
    cudaGetSymbolAddress((void**)&fA, g_featA);
    cudaGetSymbolAddress((void**)&fB, g_featB);
    cudaGetSymbolAddress((void**)&qk, g_qkv);
    cudaGetSymbolAddress((void**)&so, g_so);
    cudaGetSymbolAddress((void**)&gs, g_stats);

    k_init<<<28, 256>>>(rel);
    k_conv_down<<<896, 224>>>(x, cdw, fA, gs + OFF_BN1);

    const float* srcs[3] = {fA, fB, fA};
    float* dsts[3]       = {fB, fA, fB};
    const int proxs[3]   = {1, 0, 1};
    for (int i = 0; i < 3; i++) {
        float* bnqSt = gs + OFF_BNQ + i * 512;
        float* simSt = gs + OFF_SIM + i * 384;
        float* bnoSt = gs + OFF_BNO + i * 512;
        if (i == 0)
            k_qkv<1, 1><<<448, 256>>>(srcs[i], qkvw + i * QC * CH, qk, gs + OFF_BN1, bn1g, bn1b, bnqSt);
        else if (i == 1)
            k_qkv<0, 0><<<448, 256>>>(srcs[i], qkvw + i * QC * CH, qk, gs, bn1g, bn1b, bnqSt);
        else
            k_qkv<1, 0><<<448, 256>>>(srcs[i], qkvw + i * QC * CH, qk, gs, bn1g, bn1b, bnqSt);
        k_simstats2<<<448, 256>>>(qk, i, bnqSt, bqg + i * 256, bqb + i * 256, simSt);
        k_attn<<<3584, 224>>>(qk, rel + i * 32 * RELW, so,
                              bnqSt, bqg + i * 256, bqb + i * 256,
                              simSt, bsg + i * 24, bsb + i * 24, bnoSt);
        if (proxs[i]) k_recombine<<<12544, 256>>>(so, dsts[i], bnoSt, bog + i * 256, bob + i * 256);
        else          k_recombine_t<<<1024, 256>>>(so, dsts[i], bnoSt, bog + i * 256, bob + i * 256);
    }

    k_conv_up<<<896, 224>>>(fB, cuw, qk, gs + OFF_BN2);
    k_final<<<6272, 256>>>((const float4*)x, (const float4*)qk, rw, (float4*)out,
                           gs + OFF_BN2, bn2g, bn2b);
}

// round 14
// speedup vs baseline: 1.0014x; 1.0014x over previous
#include <cuda_runtime.h>

#define NN 8
#define CIN 256
#define LTOT 3136
#define CH 128
#define GG 8
#define HH 56
#define NB 448          // NN*56
#define QC 256
#define RELW 111
#define INV25088 (1.f / 25088.f)

// ---------------- device scratch (static, no allocation) ----------------
__device__ float g_featA[NN * CH * LTOT];   // 12.8 MB
__device__ float g_featB[NN * CH * LTOT];   // 12.8 MB
__device__ float g_qkv[NB * QC * HH];       // 25.7 MB (reused for conv_up out)
__device__ float g_so[NB * QC * HH];        // 25.7 MB
__device__ float g_stats[4992];             // all BN stat accumulators (see offsets)
__device__ float g_SU[3][2][8][56];         // sliding sums of rel_q / rel_k per axial
__device__ float g_U[3][2][56][64];         // sliding pair-product sums, i-MAJOR (coalesced)

// offsets into g_stats
#define OFF_BN1 0            // 2*128
#define OFF_BNQ 256          // 3 * 512
#define OFF_SIM 1792         // 3 * 8 replicas * 48
#define OFF_BNO 2944         // 3 * 512
#define OFF_BN2 4480         // 2*256
#define STATS_TOTAL 4992

// ---------------- helpers ----------------
__device__ __forceinline__ float fast_exp(float x) {
    float y = x * 1.4426950408889634f;
    y = fmaxf(y, -120.0f);
    float n = floorf(y);
    float f = y - n;
    float p = 1.8775767e-3f;
    p = fmaf(p, f, 8.9893397e-3f);
    p = fmaf(p, f, 5.5826318e-2f);
    p = fmaf(p, f, 2.4015361e-1f);
    p = fmaf(p, f, 6.9315308e-1f);
    p = fmaf(p, f, 9.9999994e-1f);
    return p * __int_as_float(((int)n + 127) << 23);
}

// packed f32x2 ops (Blackwell FFMA2 — PTX-only pattern)
__device__ __forceinline__ unsigned long long f2pack(float lo, float hi) {
    unsigned long long r;
    asm("mov.b64 %0, {%1, %2};" : "=l"(r) : "f"(lo), "f"(hi));
    return r;
}
__device__ __forceinline__ void f2fma(unsigned long long& d, unsigned long long a,
                                      unsigned long long b) {
    asm("fma.rn.f32x2 %0, %1, %2, %0;" : "+l"(d) : "l"(a), "l"(b));
}
__device__ __forceinline__ float2 f2unpack(unsigned long long v) {
    float2 r;
    asm("mov.b64 {%0, %1}, %2;" : "=f"(r.x), "=f"(r.y) : "l"(v));
    return r;
}

// ---------------- init: parallel rel tables (all 3 axials) + zero stats ------
__global__ void k_init(const float* __restrict__ rel) {
    int bid = blockIdx.x;
    int t = threadIdx.x;
    if (bid < 24) {
        int a = bid >> 3;
        const float* rb = rel + a * 32 * RELW;
        int w = (bid & 7) * 256 + t;   // 0..2047
#pragma unroll
        for (int rep = 0; rep < 4; rep++, w += 2048) {
            if (w < 7168) {
                int s = w / 3584;
                int r = w - s * 3584;
                int P = r / 56, i = r % 56;
                int c = P >> 3, cp = P & 7;
                const float* r1 = rb + (s * 8 + c) * RELW + i;
                const float* r2 = rb + (s * 8 + cp) * RELW + i;
                float u = 0.f;
#pragma unroll
                for (int d = 0; d < 56; d++) u = fmaf(r1[d], r2[d], u);
                g_U[a][s][i][P] = u;
            } else if (w < 8064) {
                int w2 = w - 7168;
                int s = w2 / 448;
                int r = w2 - s * 448;
                int c = r / 56, i = r % 56;
                const float* rr = rb + (s * 8 + c) * RELW + i;
                float u = 0.f;
#pragma unroll
                for (int d = 0; d < 56; d++) u += rr[d];
                g_SU[a][s][c][i] = u;
            }
        }
    } else {
        for (int i = (bid - 24) * 256 + t; i < STATS_TOTAL; i += 4 * 256)
            g_stats[i] = 0.f;
    }
}

// ---------------- grouped conv down + fused bn1 stats ----------------
__global__ __launch_bounds__(224) void k_conv_down(const float* __restrict__ x,
                                                   const float* __restrict__ w,
                                                   float* __restrict__ out,
                                                   float* __restrict__ statOut) {
    __shared__ float sW[16][32];
    __shared__ float sRs[7][16], sRq[7][16];
    int lt = blockIdx.x % 14;
    int g  = (blockIdx.x / 14) % GG;
    int n  = blockIdx.x / (14 * GG);
    int t = threadIdx.x;
    for (int i = t; i < 512; i += 224) sW[i >> 5][i & 31] = w[(g * 16) * 32 + i];
    __syncthreads();
    int l = lt * 224 + t;
    float acc[16];
#pragma unroll
    for (int o = 0; o < 16; o++) acc[o] = 0.f;
    const float* xp = x + ((size_t)(n * CIN + g * 32)) * LTOT + l;
#pragma unroll 8
    for (int k = 0; k < 32; k++) {
        float xv = xp[(size_t)k * LTOT];
#pragma unroll
        for (int o = 0; o < 16; o++) acc[o] = fmaf(sW[o][k], xv, acc[o]);
    }
    float* op = out + ((size_t)(n * CH + g * 16)) * LTOT + l;
#pragma unroll
    for (int o = 0; o < 16; o++) op[(size_t)o * LTOT] = acc[o];
    int lane = t & 31, wp = t >> 5;
#pragma unroll
    for (int o = 0; o < 16; o++) {
        float v = acc[o], v2 = v * v;
#pragma unroll
        for (int off = 16; off; off >>= 1) {
            v += __shfl_xor_sync(~0u, v, off);
            v2 += __shfl_xor_sync(~0u, v2, off);
        }
        if (lane == 0) { sRs[wp][o] = v; sRq[wp][o] = v2; }
    }
    __syncthreads();
    if (t < 16) {
        float a1 = 0.f, a2 = 0.f;
#pragma unroll
        for (int w2 = 0; w2 < 7; w2++) { a1 += sRs[w2][t]; a2 += sRq[w2][t]; }
        atomicAdd(&statOut[(g * 16 + t) * 2], a1);
        atomicAdd(&statOut[(g * 16 + t) * 2 + 1], a2);
    }
}

// ---------------- QKV GEMM per b-row + inline bn1 coef + fused bn_qkv stats --
template <int PROX, int USEBN>
__global__ __launch_bounds__(256) void k_qkv(const float* __restrict__ src,
                                             const float* __restrict__ W,
                                             float* __restrict__ qkv,
                                             const float* __restrict__ inStat,
                                             const float* __restrict__ gam,
                                             const float* __restrict__ bet,
                                             float* __restrict__ statOut) {
    __shared__ float sX[128][57];      // 29184 B; reused: stats scratch + out staging
    __shared__ float sW4[256][12];     // 12288 B; coef scratch before first fill
    int b = blockIdx.x;
    int n = b / HH, wpos = b % HH;
    int t = threadIdx.x;
    float* sCA = &sW4[0][0];
    float* sCB = sCA + 128;
    if (USEBN) {
        if (t < 128) {
            float m = inStat[2 * t] * INV25088;
            float var = inStat[2 * t + 1] * INV25088 - m * m;
            float a = gam[t] * rsqrtf(var + 1e-5f);
            sCA[t] = a; sCB[t] = bet[t] - m * a;
        }
        __syncthreads();
    }
    for (int i = t; i < CH * HH; i += 256) {
        int c = i / HH, h = i - c * HH;
        size_t idx = PROX ? (((size_t)(n * CH + c) * HH + wpos) * HH + h)
                          : (((size_t)(n * CH + c) * HH + h) * HH + wpos);
        float v = src[idx];
        if (USEBN) { v = fmaf(v, sCA[c], sCB[c]); v = fmaxf(v, 0.f); }
        sX[c][h] = v;
    }
    int o0 = t & 31;
    int h0 = (t >> 5) * 7;
    unsigned long long acc01[8], acc23[8], acc45[8];
    float acc6[8];
#pragma unroll
    for (int m = 0; m < 8; m++) {
        acc01[m] = 0ull; acc23[m] = 0ull; acc45[m] = 0ull; acc6[m] = 0.f;
    }

    for (int cc = 0; cc < 128; cc += 8) {
        __syncthreads();
        for (int i = t; i < 2048; i += 256)
            sW4[i >> 3][i & 7] = W[(i >> 3) * 128 + cc + (i & 7)];
        __syncthreads();
#pragma unroll
        for (int j4 = 0; j4 < 2; j4++) {
            float4 w4[8];
#pragma unroll
            for (int m = 0; m < 8; m++)
                w4[m] = *(const float4*)&sW4[o0 + 32 * m][j4 * 4];
#pragma unroll
            for (int jj = 0; jj < 4; jj++) {
                int c = cc + j4 * 4 + jj;
                float xv[7];
#pragma unroll
                for (int u = 0; u < 7; u++) xv[u] = sX[c][h0 + u];
                unsigned long long x01 = f2pack(xv[0], xv[1]);
                unsigned long long x23 = f2pack(xv[2], xv[3]);
                unsigned long long x45 = f2pack(xv[4], xv[5]);
#pragma unroll
                for (int m = 0; m < 8; m++) {
                    float wv = (jj == 0) ? w4[m].x : (jj == 1) ? w4[m].y
                             : (jj == 2) ? w4[m].z : w4[m].w;
                    unsigned long long w2 = f2pack(wv, wv);
                    f2fma(acc01[m], w2, x01);
                    f2fma(acc23[m], w2, x23);
                    f2fma(acc45[m], w2, x45);
                    acc6[m] = fmaf(wv, xv[6], acc6[m]);
                }
            }
        }
    }
    // unpack accumulators
    float acc[8][7];
#pragma unroll
    for (int m = 0; m < 8; m++) {
        float2 a0 = f2unpack(acc01[m]);
        float2 a1 = f2unpack(acc23[m]);
        float2 a2 = f2unpack(acc45[m]);
        acc[m][0] = a0.x; acc[m][1] = a0.y;
        acc[m][2] = a1.x; acc[m][3] = a1.y;
        acc[m][4] = a2.x; acc[m][5] = a2.y;
        acc[m][6] = acc6[m];
    }
    // ---- fused stats (scratch = sX region, inputs no longer needed) ----
    __syncthreads();
    {
        float* scr = &sX[0][0];
        int wp = t >> 5;
#pragma unroll
        for (int m = 0; m < 8; m++) {
            float s = 0.f, qq = 0.f;
#pragma unroll
            for (int u = 0; u < 7; u++) { float v = acc[m][u]; s += v; qq = fmaf(v, v, qq); }
            scr[wp * 256 + o0 + 32 * m] = s;
            scr[2048 + wp * 256 + o0 + 32 * m] = qq;
        }
        __syncthreads();
        float a1 = 0.f, a2 = 0.f;
#pragma unroll
        for (int w2 = 0; w2 < 8; w2++) {
            a1 += scr[w2 * 256 + t];
            a2 += scr[2048 + w2 * 256 + t];
        }
        atomicAdd(&statOut[2 * t], a1);
        atomicAdd(&statOut[2 * t + 1], a2);
    }
    // ---- stage output through smem for coalesced global writes ----
    float* sOut = &sX[0][0];
#pragma unroll
    for (int half = 0; half < 2; half++) {
        __syncthreads();
#pragma unroll
        for (int m = 0; m < 4; m++) {
            int mm = m + 4 * half;
            int orow = o0 + 32 * m;
#pragma unroll
            for (int u = 0; u < 7; u++) sOut[orow * 57 + h0 + u] = acc[mm][u];
        }
        __syncthreads();
        float* dst = qkv + (size_t)b * (QC * HH) + half * 128 * HH;
        for (int i = t; i < 128 * HH; i += 256) {
            int o = i / HH, h = i - o * HH;
            dst[i] = sOut[o * 57 + h];
        }
    }
}

// ---------------- algebraic sim BN stats + inline bnq coef ------------------
__global__ __launch_bounds__(256, 4) void k_simstats2(const float* __restrict__ qkv, int axial,
                                                      const float* __restrict__ bnqStat,
                                                      const float* __restrict__ gam,
                                                      const float* __restrict__ bet,
                                                      float* __restrict__ simOut) {
    __shared__ float sD[128][57];
    __shared__ float sCA[256], sCB[256];
    int b = blockIdx.x;
    int t = threadIdx.x;
    {
        float m = bnqStat[2 * t] * INV25088;
        float var = bnqStat[2 * t + 1] * INV25088 - m * m;
        float a = gam[t] * rsqrtf(var + 1e-5f);
        sCA[t] = a; sCB[t] = bet[t] - m * a;
    }
    __syncthreads();
    const float* base = qkv + (size_t)b * (QC * HH);
    for (int i = t; i < 128 * HH; i += 256) {
        int lc = i / HH, h = i - lc * HH;
        int g = lc >> 4, c = lc & 15;
        int o = g * 32 + c;
        sD[lc][h] = fmaf(base[o * HH + h], sCA[o], sCB[o]);
    }
    __syncthreads();
    int g = t >> 5, lane = t & 31;
    float accG[4], accW[4];
#pragma unroll
    for (int jj = 0; jj < 4; jj++) {
        int s = jj >> 1;
        int P = lane + 32 * (jj & 1);
        int c = P >> 3, cp = P & 7;
        const float* x1 = &sD[g * 16 + s * 8 + c][0];
        const float* x2 = &sD[g * 16 + s * 8 + cp][0];
        const float* U = &g_U[axial][s][0][P];
        float gg = 0.f, ww = 0.f;
#pragma unroll
        for (int i = 0; i < 56; i++) {
            float p = x1[i] * x2[i];
            gg += p;
            ww = fmaf(p, __ldg(U + i * 64), ww);
        }
        accG[jj] = gg; accW[jj] = ww;
    }
    float pqk = 0.f, pqr = 0.f, pkr = 0.f;
    if (lane < 8) {
        const float* xq = &sD[g * 16 + lane][0];
        const float* xk = &sD[g * 16 + 8 + lane][0];
        float sq = 0.f, sk = 0.f, vq = 0.f, vk = 0.f;
#pragma unroll
        for (int i = 0; i < 56; i++) {
            sq += xq[i]; sk += xk[i];
            vq = fmaf(xq[i], __ldg(&g_SU[axial][0][lane][i]), vq);
            vk = fmaf(xk[i], __ldg(&g_SU[axial][1][lane][i]), vk);
        }
        pqk = sq * sk; pqr = vq; pkr = vk;
    }
    float ssqk = accG[0] * accG[2] + accG[1] * accG[3];
    float ssqr = accW[0] + accW[1];
    float sskr = accW[2] + accW[3];
#pragma unroll
    for (int off = 16; off; off >>= 1) {
        pqk += __shfl_xor_sync(~0u, pqk, off);
        pqr += __shfl_xor_sync(~0u, pqr, off);
        pkr += __shfl_xor_sync(~0u, pkr, off);
        ssqk += __shfl_xor_sync(~0u, ssqk, off);
        ssqr += __shfl_xor_sync(~0u, ssqr, off);
        sskr += __shfl_xor_sync(~0u, sskr, off);
    }
    if (lane == 0) {
        float* st = simOut + (b & 7) * 48;
        atomicAdd(&st[(0 * 8 + g) * 2 + 0], pqk);
        atomicAdd(&st[(0 * 8 + g) * 2 + 1], ssqk);
        atomicAdd(&st[(1 * 8 + g) * 2 + 0], pqr);
        atomicAdd(&st[(1 * 8 + g) * 2 + 1], ssqr);
        atomicAdd(&st[(2 * 8 + g) * 2 + 0], pkr);
        atomicAdd(&st[(2 * 8 + g) * 2 + 1], sskr);
    }
}

// ---------------- fused attention (R10 body), 2 b's per block ----------------
__global__ __launch_bounds__(224) void k_attn(const float* __restrict__ qkv,
                                              const float* __restrict__ rel,
                                              float* __restrict__ so,
                                              const float* __restrict__ bnqStat,
                                              const float* __restrict__ bqg,
                                              const float* __restrict__ bqb,
                                              const float* __restrict__ simStat,
                                              const float* __restrict__ bsg,
                                              const float* __restrict__ bsb,
                                              float* __restrict__ statOut) {
    __shared__ float sQ[8][57], sK[8][57];
    __shared__ __align__(16) float sVt[56][20];     // [h][c], pad 20
    __shared__ float2 sE2[8][112];                  // (QE[c][d], KE[c][110-d])
    __shared__ __align__(16) float sVEt[112][20];   // [d][c], pad 20
    __shared__ float sSim[56][57];
    __shared__ float sInv[56];
    __shared__ float sCA[32], sCB[32], sP[6];
    int g = blockIdx.x & 7;
    int bpair = blockIdx.x >> 3;
    int t = threadIdx.x;
    if (t < 32) {
        int o = g * 32 + t;
        float m = bnqStat[2 * o] * INV25088;
        float var = bnqStat[2 * o + 1] * INV25088 - m * m;
        float a = bqg[o] * rsqrtf(var + 1e-5f);
        sCA[t] = a; sCB[t] = bqb[o] - m * a;
    } else if (t < 35) {
        int p = t - 32;
        int ch = p * 8 + g;
        float s1 = 0.f, s2 = 0.f;
#pragma unroll
        for (int r = 0; r < 8; r++) { s1 += simStat[r * 48 + ch * 2]; s2 += simStat[r * 48 + ch * 2 + 1]; }
        const float invc = 1.f / (448.f * 3136.f);
        float m = s1 * invc;
        float var = s2 * invc - m * m;
        float a = bsg[ch] * rsqrtf(var + 1e-5f);
        sP[p] = a; sP[3 + p] = bsb[ch] - m * a;
    }
    // rel tables: loaded once, shared by both b's
    for (int i = t; i < 8 * 111; i += 224) {
        int c = i / 111, d = i - c * 111;
        sE2[c][d] = make_float2(rel[c * RELW + d], rel[(8 + c) * RELW + (110 - d)]);
    }
    for (int i = t; i < 16 * 111; i += 224) {
        int c = i / 111, d = i - c * 111;
        sVEt[d][c] = rel[(16 + c) * RELW + d];
    }
    __syncthreads();   // coefs + rel tables visible to ALL threads before use

    for (int rep = 0; rep < 2; rep++) {
        int b = bpair * 2 + rep;
        if (rep) __syncthreads();   // previous iteration fully done (incl. sRed reads)
        const float* base = qkv + (size_t)b * (QC * HH) + g * 32 * HH;
        for (int i = t; i < 32 * HH; i += 224) {
            int c = i / HH, h = i - c * HH;
            float v = fmaf(base[c * HH + h], sCA[c], sCB[c]);
            if (c < 8) sQ[c][h] = v;
            else if (c < 16) sK[c - 8][h] = v;
            else sVt[h][c - 16] = v;
        }
        __syncthreads();
        float aqk = sP[0], aqr = sP[1], akr = sP[2];
        float bias = sP[3] + sP[4] + sP[5];
        int i0 = t >> 2, jt = t & 3;
        float qv[8];
#pragma unroll
        for (int c = 0; c < 8; c++) qv[c] = sQ[c][i0];
        float lg[14];
#pragma unroll
        for (int u = 0; u < 14; u++) {
            int j = jt * 14 + u;
            int d1 = i0 - j + 55;
            float qk = 0.f, qr = 0.f, kr = 0.f;
#pragma unroll
            for (int c = 0; c < 8; c++) {
                float kj = sK[c][j];
                float2 e2 = sE2[c][d1];
                qk = fmaf(qv[c], kj, qk);
                qr = fmaf(qv[c], e2.x, qr);
                kr = fmaf(kj, e2.y, kr);
            }
            lg[u] = fmaf(aqk, qk, fmaf(aqr, qr, fmaf(akr, kr, bias)));
        }
        float m = -1e30f;
#pragma unroll
        for (int u = 0; u < 14; u++) m = fmaxf(m, lg[u]);
        m = fmaxf(m, __shfl_xor_sync(~0u, m, 1));
        m = fmaxf(m, __shfl_xor_sync(~0u, m, 2));
        float s = 0.f;
#pragma unroll
        for (int u = 0; u < 14; u++) { lg[u] = fast_exp(lg[u] - m); s += lg[u]; }
        s += __shfl_xor_sync(~0u, s, 1);
        s += __shfl_xor_sync(~0u, s, 2);
#pragma unroll
        for (int u = 0; u < 14; u++) sSim[i0][jt * 14 + u] = lg[u];
        if (jt == 0) sInv[i0] = 1.f / s;
        __syncthreads();
        int c4 = t / 56, ii = t % 56;
        unsigned long long a01 = 0ull, a23 = 0ull, e01 = 0ull, e23 = 0ull;
#pragma unroll 4
        for (int j = 0; j < 56; j++) {
            float e = sSim[ii][j];
            unsigned long long ee = f2pack(e, e);
            ulonglong2 v2 = *(const ulonglong2*)&sVt[j][c4 * 4];
            ulonglong2 ve2 = *(const ulonglong2*)&sVEt[ii - j + 55][c4 * 4];
            f2fma(a01, ee, v2.x);
            f2fma(a23, ee, v2.y);
            f2fma(e01, ee, ve2.x);
            f2fma(e23, ee, ve2.y);
        }
        float inv = sInv[ii];
        float2 ua = f2unpack(a01), ub = f2unpack(a23);
        float2 uc = f2unpack(e01), ud = f2unpack(e23);
        float vals[8];
        vals[0] = ua.x * inv; vals[1] = uc.x * inv;
        vals[2] = ua.y * inv; vals[3] = uc.y * inv;
        vals[4] = ub.x * inv; vals[5] = ud.x * inv;
        vals[6] = ub.y * inv; vals[7] = ud.y * inv;
        float* ob = so + (size_t)b * (QC * HH) + (g * 32) * HH + ii;
#pragma unroll
        for (int z = 0; z < 4; z++) {
            int c = c4 * 4 + z;
            ob[(2 * c) * HH] = vals[z * 2 + 0];
            ob[(2 * c + 1) * HH] = vals[z * 2 + 1];
        }
        __syncthreads();
        {
            float* sRed = &sSim[0][0];
#pragma unroll
            for (int z = 0; z < 4; z++) {
                sRed[t * 8 + z * 2 + 0] = vals[z * 2 + 0];
                sRed[t * 8 + z * 2 + 1] = vals[z * 2 + 1];
            }
            __syncthreads();
            if (t < 32) {
                int c4r = t >> 3, z = (t >> 1) & 3, p = t & 1;
                int off = z * 2 + p;
                float a1 = 0.f, a2 = 0.f;
                for (int ii2 = 0; ii2 < 56; ii2++) {
                    float v = sRed[(c4r * 56 + ii2) * 8 + off];
                    a1 += v; a2 = fmaf(v, v, a2);
                }
                atomicAdd(&statOut[2 * (g * 32 + t)], a1);
                atomicAdd(&statOut[2 * (g * 32 + t) + 1], a2);
            }
        }
    }
}

// ---------------- bn_out apply + pair sum, prox=1 (inline coef) -------------
__global__ __launch_bounds__(256) void k_recombine(const float* __restrict__ so,
                                                   float* __restrict__ dst,
                                                   const float* __restrict__ st,
                                                   const float* __restrict__ bog,
                                                   const float* __restrict__ bob) {
    int idx = blockIdx.x * 256 + threadIdx.x;
    if (idx >= NB * CH * HH) return;
    int h = idx % HH;
    int cc = (idx / HH) % CH;
    int row = idx / (HH * CH);
    int o = 2 * cc;
    float m0 = st[2 * o] * INV25088;
    float v0 = st[2 * o + 1] * INV25088 - m0 * m0;
    float a0 = bog[o] * rsqrtf(v0 + 1e-5f);
    float b0 = bob[o] - m0 * a0;
    float m1 = st[2 * o + 2] * INV25088;
    float v1 = st[2 * o + 3] * INV25088 - m1 * m1;
    float a1 = bog[o + 1] * rsqrtf(v1 + 1e-5f);
    float b1 = bob[o + 1] - m1 * a1;
    float v = fmaf(so[(size_t)row * (QC * HH) + o * HH + h], a0, b0) +
              fmaf(so[(size_t)row * (QC * HH) + (o + 1) * HH + h], a1, b1);
    int n = row / HH, wpos = row % HH;
    dst[((size_t)(n * CH + cc) * HH + wpos) * HH + h] = v;
}

// ---------------- bn_out apply + pair sum, prox=0 (smem transpose) ----------
__global__ __launch_bounds__(256) void k_recombine_t(const float* __restrict__ so,
                                                     float* __restrict__ dst,
                                                     const float* __restrict__ st,
                                                     const float* __restrict__ bog,
                                                     const float* __restrict__ bob) {
    __shared__ float sT[56][57];
    int cc = blockIdx.x & 127;
    int n = blockIdx.x >> 7;
    int t = threadIdx.x;
    int o = 2 * cc;
    float m0 = st[2 * o] * INV25088;
    float v0 = st[2 * o + 1] * INV25088 - m0 * m0;
    float a0 = bog[o] * rsqrtf(v0 + 1e-5f);
    float b0 = bob[o] - m0 * a0;
    float m1 = st[2 * o + 2] * INV25088;
    float v1 = st[2 * o + 3] * INV25088 - m1 * m1;
    float a1 = bog[o + 1] * rsqrtf(v1 + 1e-5f);
    float b1 = bob[o + 1] - m1 * a1;
    const float* base = so + ((size_t)n * HH) * (QC * HH);
    for (int i = t; i < 56 * 56; i += 256) {
        int w = i / 56, h = i - w * 56;
        const float* r = base + (size_t)w * (QC * HH) + o * HH + h;
        sT[w][h] = fmaf(r[0], a0, b0) + fmaf(r[HH], a1, b1);
    }
    __syncthreads();
    float* d = dst + ((size_t)(n * CH + cc)) * LTOT;
    for (int i = t; i < 56 * 56; i += 256) {
        int a = i / 56, bb = i - a * 56;
        d[i] = sT[bb][a];
    }
}

// ---------------- grouped conv up + fused bn2 stats -----------------------
__global__ __launch_bounds__(224) void k_conv_up(const float* __restrict__ hbuf,
                                                 const float* __restrict__ w,
                                                 float* __restrict__ out,
                                                 float* __restrict__ statOut) {
    __shared__ float sW[32][16];
    __shared__ float sRs[7][32], sRq[7][32];
    int lt = blockIdx.x % 14;
    int g  = (blockIdx.x / 14) % GG;
    int n  = blockIdx.x / (14 * GG);
    int t = threadIdx.x;
    for (int i = t; i < 512; i += 224) sW[i >> 4][i & 15] = w[(g * 32) * 16 + i];
    __syncthreads();
    int l = lt * 224 + t;
    float acc[32];
#pragma unroll
    for (int o = 0; o < 32; o++) acc[o] = 0.f;
    const float* hp = hbuf + ((size_t)(n * CH + g * 16)) * LTOT + l;
#pragma unroll 4
    for (int k = 0; k < 16; k++) {
        float hv = fmaxf(hp[(size_t)k * LTOT], 0.f);
#pragma unroll
        for (int o = 0; o < 32; o++) acc[o] = fmaf(sW[o][k], hv, acc[o]);
    }
    float* op = out + ((size_t)(n * CIN + g * 32)) * LTOT + l;
#pragma unroll
    for (int o = 0; o < 32; o++) op[(size_t)o * LTOT] = acc[o];
    int lane = t & 31, wp = t >> 5;
#pragma unroll
    for (int o = 0; o < 32; o++) {
        float v = acc[o], v2 = v * v;
#pragma unroll
        for (int off = 16; off; off >>= 1) {
            v += __shfl_xor_sync(~0u, v, off);
            v2 += __shfl_xor_sync(~0u, v2, off);
        }
        if (lane == 0) { sRs[wp][o] = v; sRq[wp][o] = v2; }
    }
    __syncthreads();
    if (t < 32) {
        float a1 = 0.f, a2 = 0.f;
#pragma unroll
        for (int w2 = 0; w2 < 7; w2++) { a1 += sRs[w2][t]; a2 += sRq[w2][t]; }
        atomicAdd(&statOut[(g * 32 + t) * 2], a1);
        atomicAdd(&statOut[(g * 32 + t) * 2 + 1], a2);
    }
}

// ---------------- final: relu(x + bn2(conv_up) * rw), float4, inline coef ----
__global__ __launch_bounds__(256) void k_final(const float4* __restrict__ x,
                                               const float4* __restrict__ cu,
                                               const float* __restrict__ rw,
                                               float4* __restrict__ out,
                                               const float* __restrict__ st,
                                               const float* __restrict__ g2,
                                               const float* __restrict__ b2) {
    int idx = blockIdx.x * 256 + threadIdx.x;
    if (idx >= NN * CIN * (LTOT / 4)) return;
    int ch = (idx / (LTOT / 4)) & 255;
    float m = st[2 * ch] * INV25088;
    float var = st[2 * ch + 1] * INV25088 - m * m;
    float a = g2[ch] * rsqrtf(var + 1e-5f);
    float bb = b2[ch] - m * a;
    float wv = __ldg(rw);
    float4 c = cu[idx], xx = x[idx], r;
    r.x = fmaxf(fmaf(fmaf(c.x, a, bb), wv, xx.x), 0.f);
    r.y = fmaxf(fmaf(fmaf(c.y, a, bb), wv, xx.y), 0.f);
    r.z = fmaxf(fmaf(fmaf(c.z, a, bb), wv, xx.z), 0.f);
    r.w = fmaxf(fmaf(fmaf(c.w, a, bb), wv, xx.w), 0.f);
    out[idx] = r;
}

// ---------------- launch ----------------
extern "C" void kernel_launch(void* const* d_in, const int* in_sizes, int n_in,
                              void* d_out, int out_size) {
    const float* x    = (const float*)d_in[0];
    const float* cdw  = (const float*)d_in[1];
    const float* bn1g = (const float*)d_in[2];
    const float* bn1b = (const float*)d_in[3];
    const float* qkvw = (const float*)d_in[4];
    const float* bqg  = (const float*)d_in[5];
    const float* bqb  = (const float*)d_in[6];
    const float* bsg  = (const float*)d_in[7];
    const float* bsb  = (const float*)d_in[8];
    const float* bog  = (const float*)d_in[9];
    const float* bob  = (const float*)d_in[10];
    const float* rel  = (const float*)d_in[11];
    const float* cuw  = (const float*)d_in[12];
    const float* bn2g = (const float*)d_in[13];
    const float* bn2b = (const float*)d_in[14];
    const float* rw   = (const float*)d_in[15];
    float* out = (float*)d_out;

    float *fA, *fB, *qk, *so, *gs;
    cudaGetSymbolAddress((void**)&fA, g_featA);
    cudaGetSymbolAddress((void**)&fB, g_featB);
    cudaGetSymbolAddress((void**)&qk, g_qkv);
    cudaGetSymbolAddress((void**)&so, g_so);
    cudaGetSymbolAddress((void**)&gs, g_stats);

    k_init<<<28, 256>>>(rel);
    k_conv_down<<<896, 224>>>(x, cdw, fA, gs + OFF_BN1);

    const float* srcs[3] = {fA, fB, fA};
    float* dsts[3]       = {fB, fA, fB};
    const int proxs[3]   = {1, 0, 1};
    for (int i = 0; i < 3; i++) {
        float* bnqSt = gs + OFF_BNQ + i * 512;
        float* simSt = gs + OFF_SIM + i * 384;
        float* bnoSt = gs + OFF_BNO + i * 512;
        if (i == 0)
            k_qkv<1, 1><<<448, 256>>>(srcs[i], qkvw + i * QC * CH, qk, gs + OFF_BN1, bn1g, bn1b, bnqSt);
        else if (i == 1)
            k_qkv<0, 0><<<448, 256>>>(srcs[i], qkvw + i * QC * CH, qk, gs, bn1g, bn1b, bnqSt);
        else
            k_qkv<1, 0><<<448, 256>>>(srcs[i], qkvw + i * QC * CH, qk, gs, bn1g, bn1b, bnqSt);
        k_simstats2<<<448, 256>>>(qk, i, bnqSt, bqg + i * 256, bqb + i * 256, simSt);
        k_attn<<<1792, 224>>>(qk, rel + i * 32 * RELW, so,
                              bnqSt, bqg + i * 256, bqb + i * 256,
                              simSt, bsg + i * 24, bsb + i * 24, bnoSt);
        if (proxs[i]) k_recombine<<<12544, 256>>>(so, dsts[i], bnoSt, bog + i * 256, bob + i * 256);
        else          k_recombine_t<<<1024, 256>>>(so, dsts[i], bnoSt, bog + i * 256, bob + i * 256);
    }

    k_conv_up<<<896, 224>>>(fB, cuw, qk, gs + OFF_BN2);
    k_final<<<6272, 256>>>((const float4*)x, (const float4*)qk, rw, (float4*)out,
                           gs + OFF_BN2, bn2g, bn2b);
}

// round 15
// speedup vs baseline: 1.0190x; 1.0175x over previous
#include <cuda_runtime.h>

#define NN 8
#define CIN 256
#define LTOT 3136
#define CH 128
#define GG 8
#define HH 56
#define NB 448          // NN*56
#define QC 256
#define RELW 111
#define INV25088 (1.f / 25088.f)

// ---------------- device scratch (static, no allocation) ----------------
__device__ float g_featA[NN * CH * LTOT];   // 12.8 MB
__device__ float g_featB[NN * CH * LTOT];   // 12.8 MB
__device__ float g_qkv[NB * QC * HH];       // 25.7 MB (reused for conv_up out)
__device__ float g_so[NB * QC * HH];        // 25.7 MB
__device__ float g_stats[4992];             // all BN stat accumulators (see offsets)
__device__ float g_SU[3][2][8][56];         // sliding sums of rel_q / rel_k per axial
__device__ float g_U[3][2][56][64];         // sliding pair-product sums, i-MAJOR (coalesced)

// offsets into g_stats
#define OFF_BN1 0            // 2*128
#define OFF_BNQ 256          // 3 * 512
#define OFF_SIM 1792         // 3 * 8 replicas * 48
#define OFF_BNO 2944         // 3 * 512
#define OFF_BN2 4480         // 2*256
#define STATS_TOTAL 4992

// ---------------- helpers ----------------
__device__ __forceinline__ float fast_exp(float x) {
    float y = x * 1.4426950408889634f;
    y = fmaxf(y, -120.0f);
    float n = floorf(y);
    float f = y - n;
    float p = 1.8775767e-3f;
    p = fmaf(p, f, 8.9893397e-3f);
    p = fmaf(p, f, 5.5826318e-2f);
    p = fmaf(p, f, 2.4015361e-1f);
    p = fmaf(p, f, 6.9315308e-1f);
    p = fmaf(p, f, 9.9999994e-1f);
    return p * __int_as_float(((int)n + 127) << 23);
}

// packed f32x2 ops (Blackwell FFMA2 — PTX-only pattern)
__device__ __forceinline__ unsigned long long f2pack(float lo, float hi) {
    unsigned long long r;
    asm("mov.b64 %0, {%1, %2};" : "=l"(r) : "f"(lo), "f"(hi));
    return r;
}
__device__ __forceinline__ void f2fma(unsigned long long& d, unsigned long long a,
                                      unsigned long long b) {
    asm("fma.rn.f32x2 %0, %1, %2, %0;" : "+l"(d) : "l"(a), "l"(b));
}
__device__ __forceinline__ float2 f2unpack(unsigned long long v) {
    float2 r;
    asm("mov.b64 {%0, %1}, %2;" : "=f"(r.x), "=f"(r.y) : "l"(v));
    return r;
}

// ---------------- init: parallel rel tables (all 3 axials) + zero stats ------
__global__ void k_init(const float* __restrict__ rel) {
    int bid = blockIdx.x;
    int t = threadIdx.x;
    if (bid < 24) {
        int a = bid >> 3;
        const float* rb = rel + a * 32 * RELW;
        int w = (bid & 7) * 256 + t;   // 0..2047
#pragma unroll
        for (int rep = 0; rep < 4; rep++, w += 2048) {
            if (w < 7168) {
                int s = w / 3584;
                int r = w - s * 3584;
                int P = r / 56, i = r % 56;
                int c = P >> 3, cp = P & 7;
                const float* r1 = rb + (s * 8 + c) * RELW + i;
                const float* r2 = rb + (s * 8 + cp) * RELW + i;
                float u = 0.f;
#pragma unroll
                for (int d = 0; d < 56; d++) u = fmaf(r1[d], r2[d], u);
                g_U[a][s][i][P] = u;
            } else if (w < 8064) {
                int w2 = w - 7168;
                int s = w2 / 448;
                int r = w2 - s * 448;
                int c = r / 56, i = r % 56;
                const float* rr = rb + (s * 8 + c) * RELW + i;
                float u = 0.f;
#pragma unroll
                for (int d = 0; d < 56; d++) u += rr[d];
                g_SU[a][s][c][i] = u;
            }
        }
    } else {
        for (int i = (bid - 24) * 256 + t; i < STATS_TOTAL; i += 4 * 256)
            g_stats[i] = 0.f;
    }
}

// ---------------- grouped conv down + fused bn1 stats ----------------
__global__ __launch_bounds__(224) void k_conv_down(const float* __restrict__ x,
                                                   const float* __restrict__ w,
                                                   float* __restrict__ out,
                                                   float* __restrict__ statOut) {
    __shared__ float sW[16][32];
    __shared__ float sRs[7][16], sRq[7][16];
    int lt = blockIdx.x % 14;
    int g  = (blockIdx.x / 14) % GG;
    int n  = blockIdx.x / (14 * GG);
    int t = threadIdx.x;
    for (int i = t; i < 512; i += 224) sW[i >> 5][i & 31] = w[(g * 16) * 32 + i];
    __syncthreads();
    int l = lt * 224 + t;
    float acc[16];
#pragma unroll
    for (int o = 0; o < 16; o++) acc[o] = 0.f;
    const float* xp = x + ((size_t)(n * CIN + g * 32)) * LTOT + l;
#pragma unroll 8
    for (int k = 0; k < 32; k++) {
        float xv = xp[(size_t)k * LTOT];
#pragma unroll
        for (int o = 0; o < 16; o++) acc[o] = fmaf(sW[o][k], xv, acc[o]);
    }
    float* op = out + ((size_t)(n * CH + g * 16)) * LTOT + l;
#pragma unroll
    for (int o = 0; o < 16; o++) op[(size_t)o * LTOT] = acc[o];
    int lane = t & 31, wp = t >> 5;
#pragma unroll
    for (int o = 0; o < 16; o++) {
        float v = acc[o], v2 = v * v;
#pragma unroll
        for (int off = 16; off; off >>= 1) {
            v += __shfl_xor_sync(~0u, v, off);
            v2 += __shfl_xor_sync(~0u, v2, off);
        }
        if (lane == 0) { sRs[wp][o] = v; sRq[wp][o] = v2; }
    }
    __syncthreads();
    if (t < 16) {
        float a1 = 0.f, a2 = 0.f;
#pragma unroll
        for (int w2 = 0; w2 < 7; w2++) { a1 += sRs[w2][t]; a2 += sRq[w2][t]; }
        atomicAdd(&statOut[(g * 16 + t) * 2], a1);
        atomicAdd(&statOut[(g * 16 + t) * 2 + 1], a2);
    }
}

// ---------------- QKV GEMM per b-row + inline bn1 coef + fused bn_qkv stats --
// All gathers contiguous (PROX-1 style); axial-1 uses a transposed src buffer.
template <int USEBN>
__global__ __launch_bounds__(256) void k_qkv(const float* __restrict__ src,
                                             const float* __restrict__ W,
                                             float* __restrict__ qkv,
                                             const float* __restrict__ inStat,
                                             const float* __restrict__ gam,
                                             const float* __restrict__ bet,
                                             float* __restrict__ statOut) {
    __shared__ float sX[128][57];      // 29184 B; reused: stats scratch + out staging
    __shared__ float sW4[256][12];     // 12288 B; coef scratch before first fill
    int b = blockIdx.x;
    int n = b / HH, wpos = b % HH;
    int t = threadIdx.x;
    float* sCA = &sW4[0][0];
    float* sCB = sCA + 128;
    if (USEBN) {
        if (t < 128) {
            float m = inStat[2 * t] * INV25088;
            float var = inStat[2 * t + 1] * INV25088 - m * m;
            float a = gam[t] * rsqrtf(var + 1e-5f);
            sCA[t] = a; sCB[t] = bet[t] - m * a;
        }
        __syncthreads();
    }
    for (int i = t; i < CH * HH; i += 256) {
        int c = i / HH, h = i - c * HH;
        float v = src[((size_t)(n * CH + c) * HH + wpos) * HH + h];
        if (USEBN) { v = fmaf(v, sCA[c], sCB[c]); v = fmaxf(v, 0.f); }
        sX[c][h] = v;
    }
    int o0 = t & 31;
    int h0 = (t >> 5) * 7;
    unsigned long long acc01[8], acc23[8], acc45[8];
    float acc6[8];
#pragma unroll
    for (int m = 0; m < 8; m++) {
        acc01[m] = 0ull; acc23[m] = 0ull; acc45[m] = 0ull; acc6[m] = 0.f;
    }

    for (int cc = 0; cc < 128; cc += 8) {
        __syncthreads();
        for (int i = t; i < 2048; i += 256)
            sW4[i >> 3][i & 7] = W[(i >> 3) * 128 + cc + (i & 7)];
        __syncthreads();
#pragma unroll
        for (int j4 = 0; j4 < 2; j4++) {
            float4 w4[8];
#pragma unroll
            for (int m = 0; m < 8; m++)
                w4[m] = *(const float4*)&sW4[o0 + 32 * m][j4 * 4];
#pragma unroll
            for (int jj = 0; jj < 4; jj++) {
                int c = cc + j4 * 4 + jj;
                float xv[7];
#pragma unroll
                for (int u = 0; u < 7; u++) xv[u] = sX[c][h0 + u];
                unsigned long long x01 = f2pack(xv[0], xv[1]);
                unsigned long long x23 = f2pack(xv[2], xv[3]);
                unsigned long long x45 = f2pack(xv[4], xv[5]);
#pragma unroll
                for (int m = 0; m < 8; m++) {
                    float wv = (jj == 0) ? w4[m].x : (jj == 1) ? w4[m].y
                             : (jj == 2) ? w4[m].z : w4[m].w;
                    unsigned long long w2 = f2pack(wv, wv);
                    f2fma(acc01[m], w2, x01);
                    f2fma(acc23[m], w2, x23);
                    f2fma(acc45[m], w2, x45);
                    acc6[m] = fmaf(wv, xv[6], acc6[m]);
                }
            }
        }
    }
    // unpack accumulators
    float acc[8][7];
#pragma unroll
    for (int m = 0; m < 8; m++) {
        float2 a0 = f2unpack(acc01[m]);
        float2 a1 = f2unpack(acc23[m]);
        float2 a2 = f2unpack(acc45[m]);
        acc[m][0] = a0.x; acc[m][1] = a0.y;
        acc[m][2] = a1.x; acc[m][3] = a1.y;
        acc[m][4] = a2.x; acc[m][5] = a2.y;
        acc[m][6] = acc6[m];
    }
    // ---- fused stats (scratch = sX region, inputs no longer needed) ----
    __syncthreads();
    {
        float* scr = &sX[0][0];
        int wp = t >> 5;
#pragma unroll
        for (int m = 0; m < 8; m++) {
            float s = 0.f, qq = 0.f;
#pragma unroll
            for (int u = 0; u < 7; u++) { float v = acc[m][u]; s += v; qq = fmaf(v, v, qq); }
            scr[wp * 256 + o0 + 32 * m] = s;
            scr[2048 + wp * 256 + o0 + 32 * m] = qq;
        }
        __syncthreads();
        float a1 = 0.f, a2 = 0.f;
#pragma unroll
        for (int w2 = 0; w2 < 8; w2++) {
            a1 += scr[w2 * 256 + t];
            a2 += scr[2048 + w2 * 256 + t];
        }
        atomicAdd(&statOut[2 * t], a1);
        atomicAdd(&statOut[2 * t + 1], a2);
    }
    // ---- stage output through smem for coalesced global writes ----
    float* sOut = &sX[0][0];
#pragma unroll
    for (int half = 0; half < 2; half++) {
        __syncthreads();
#pragma unroll
        for (int m = 0; m < 4; m++) {
            int mm = m + 4 * half;
            int orow = o0 + 32 * m;
#pragma unroll
            for (int u = 0; u < 7; u++) sOut[orow * 57 + h0 + u] = acc[mm][u];
        }
        __syncthreads();
        float* dst = qkv + (size_t)b * (QC * HH) + half * 128 * HH;
        for (int i = t; i < 128 * HH; i += 256) {
            int o = i / HH, h = i - o * HH;
            dst[i] = sOut[o * 57 + h];
        }
    }
}

// ---------------- algebraic sim BN stats + inline bnq coef ------------------
__global__ __launch_bounds__(256, 4) void k_simstats2(const float* __restrict__ qkv, int axial,
                                                      const float* __restrict__ bnqStat,
                                                      const float* __restrict__ gam,
                                                      const float* __restrict__ bet,
                                                      float* __restrict__ simOut) {
    __shared__ float sD[128][57];
    __shared__ float sCA[256], sCB[256];
    int b = blockIdx.x;
    int t = threadIdx.x;
    {
        float m = bnqStat[2 * t] * INV25088;
        float var = bnqStat[2 * t + 1] * INV25088 - m * m;
        float a = gam[t] * rsqrtf(var + 1e-5f);
        sCA[t] = a; sCB[t] = bet[t] - m * a;
    }
    __syncthreads();
    const float* base = qkv + (size_t)b * (QC * HH);
    for (int i = t; i < 128 * HH; i += 256) {
        int lc = i / HH, h = i - lc * HH;
        int g = lc >> 4, c = lc & 15;
        int o = g * 32 + c;
        sD[lc][h] = fmaf(base[o * HH + h], sCA[o], sCB[o]);
    }
    __syncthreads();
    int g = t >> 5, lane = t & 31;
    float accG[4], accW[4];
#pragma unroll
    for (int jj = 0; jj < 4; jj++) {
        int s = jj >> 1;
        int P = lane + 32 * (jj & 1);
        int c = P >> 3, cp = P & 7;
        const float* x1 = &sD[g * 16 + s * 8 + c][0];
        const float* x2 = &sD[g * 16 + s * 8 + cp][0];
        const float* U = &g_U[axial][s][0][P];
        float gg = 0.f, ww = 0.f;
#pragma unroll
        for (int i = 0; i < 56; i++) {
            float p = x1[i] * x2[i];
            gg += p;
            ww = fmaf(p, __ldg(U + i * 64), ww);
        }
        accG[jj] = gg; accW[jj] = ww;
    }
    float pqk = 0.f, pqr = 0.f, pkr = 0.f;
    if (lane < 8) {
        const float* xq = &sD[g * 16 + lane][0];
        const float* xk = &sD[g * 16 + 8 + lane][0];
        float sq = 0.f, sk = 0.f, vq = 0.f, vk = 0.f;
#pragma unroll
        for (int i = 0; i < 56; i++) {
            sq += xq[i]; sk += xk[i];
            vq = fmaf(xq[i], __ldg(&g_SU[axial][0][lane][i]), vq);
            vk = fmaf(xk[i], __ldg(&g_SU[axial][1][lane][i]), vk);
        }
        pqk = sq * sk; pqr = vq; pkr = vk;
    }
    float ssqk = accG[0] * accG[2] + accG[1] * accG[3];
    float ssqr = accW[0] + accW[1];
    float sskr = accW[2] + accW[3];
#pragma unroll
    for (int off = 16; off; off >>= 1) {
        pqk += __shfl_xor_sync(~0u, pqk, off);
        pqr += __shfl_xor_sync(~0u, pqr, off);
        pkr += __shfl_xor_sync(~0u, pkr, off);
        ssqk += __shfl_xor_sync(~0u, ssqk, off);
        ssqr += __shfl_xor_sync(~0u, ssqr, off);
        sskr += __shfl_xor_sync(~0u, sskr, off);
    }
    if (lane == 0) {
        float* st = simOut + (b & 7) * 48;
        atomicAdd(&st[(0 * 8 + g) * 2 + 0], pqk);
        atomicAdd(&st[(0 * 8 + g) * 2 + 1], ssqk);
        atomicAdd(&st[(1 * 8 + g) * 2 + 0], pqr);
        atomicAdd(&st[(1 * 8 + g) * 2 + 1], ssqr);
        atomicAdd(&st[(2 * 8 + g) * 2 + 0], pkr);
        atomicAdd(&st[(2 * 8 + g) * 2 + 1], sskr);
    }
}

// ---------------- fused attention (R10 winner: 1 b per block) ----------------
__global__ __launch_bounds__(224) void k_attn(const float* __restrict__ qkv,
                                              const float* __restrict__ rel,
                                              float* __restrict__ so,
                                              const float* __restrict__ bnqStat,
                                              const float* __restrict__ bqg,
                                              const float* __restrict__ bqb,
                                              const float* __restrict__ simStat,
                                              const float* __restrict__ bsg,
                                              const float* __restrict__ bsb,
                                              float* __restrict__ statOut) {
    __shared__ float sQ[8][57], sK[8][57];
    __shared__ __align__(16) float sVt[56][20];     // [h][c], pad 20
    __shared__ float2 sE2[8][112];                  // (QE[c][d], KE[c][110-d])
    __shared__ __align__(16) float sVEt[112][20];   // [d][c], pad 20
    __shared__ float sSim[56][57];
    __shared__ float sInv[56];
    __shared__ float sCA[32], sCB[32], sP[6];
    int g = blockIdx.x & 7;
    int b = blockIdx.x >> 3;
    int t = threadIdx.x;
    if (t < 32) {
        int o = g * 32 + t;
        float m = bnqStat[2 * o] * INV25088;
        float var = bnqStat[2 * o + 1] * INV25088 - m * m;
        float a = bqg[o] * rsqrtf(var + 1e-5f);
        sCA[t] = a; sCB[t] = bqb[o] - m * a;
    } else if (t < 35) {
        int p = t - 32;
        int ch = p * 8 + g;
        float s1 = 0.f, s2 = 0.f;
#pragma unroll
        for (int r = 0; r < 8; r++) { s1 += simStat[r * 48 + ch * 2]; s2 += simStat[r * 48 + ch * 2 + 1]; }
        const float invc = 1.f / (448.f * 3136.f);
        float m = s1 * invc;
        float var = s2 * invc - m * m;
        float a = bsg[ch] * rsqrtf(var + 1e-5f);
        sP[p] = a; sP[3 + p] = bsb[ch] - m * a;
    }
    __syncthreads();
    const float* base = qkv + (size_t)b * (QC * HH) + g * 32 * HH;
    for (int i = t; i < 32 * HH; i += 224) {
        int c = i / HH, h = i - c * HH;
        float v = fmaf(base[c * HH + h], sCA[c], sCB[c]);
        if (c < 8) sQ[c][h] = v;
        else if (c < 16) sK[c - 8][h] = v;
        else sVt[h][c - 16] = v;
    }
    for (int i = t; i < 8 * 111; i += 224) {
        int c = i / 111, d = i - c * 111;
        sE2[c][d] = make_float2(rel[c * RELW + d], rel[(8 + c) * RELW + (110 - d)]);
    }
    for (int i = t; i < 16 * 111; i += 224) {
        int c = i / 111, d = i - c * 111;
        sVEt[d][c] = rel[(16 + c) * RELW + d];
    }
    __syncthreads();
    float aqk = sP[0], aqr = sP[1], akr = sP[2];
    float bias = sP[3] + sP[4] + sP[5];
    int i0 = t >> 2, jt = t & 3;
    float qv[8];
#pragma unroll
    for (int c = 0; c < 8; c++) qv[c] = sQ[c][i0];
    float lg[14];
#pragma unroll
    for (int u = 0; u < 14; u++) {
        int j = jt * 14 + u;
        int d1 = i0 - j + 55;
        float qk = 0.f, qr = 0.f, kr = 0.f;
#pragma unroll
        for (int c = 0; c < 8; c++) {
            float kj = sK[c][j];
            float2 e2 = sE2[c][d1];
            qk = fmaf(qv[c], kj, qk);
            qr = fmaf(qv[c], e2.x, qr);
            kr = fmaf(kj, e2.y, kr);
        }
        lg[u] = fmaf(aqk, qk, fmaf(aqr, qr, fmaf(akr, kr, bias)));
    }
    float m = -1e30f;
#pragma unroll
    for (int u = 0; u < 14; u++) m = fmaxf(m, lg[u]);
    m = fmaxf(m, __shfl_xor_sync(~0u, m, 1));
    m = fmaxf(m, __shfl_xor_sync(~0u, m, 2));
    float s = 0.f;
#pragma unroll
    for (int u = 0; u < 14; u++) { lg[u] = fast_exp(lg[u] - m); s += lg[u]; }
    s += __shfl_xor_sync(~0u, s, 1);
    s += __shfl_xor_sync(~0u, s, 2);
#pragma unroll
    for (int u = 0; u < 14; u++) sSim[i0][jt * 14 + u] = lg[u];
    if (jt == 0) sInv[i0] = 1.f / s;
    __syncthreads();
    int c4 = t / 56, ii = t % 56;
    unsigned long long a01 = 0ull, a23 = 0ull, e01 = 0ull, e23 = 0ull;
#pragma unroll 4
    for (int j = 0; j < 56; j++) {
        float e = sSim[ii][j];
        unsigned long long ee = f2pack(e, e);
        ulonglong2 v2 = *(const ulonglong2*)&sVt[j][c4 * 4];
        ulonglong2 ve2 = *(const ulonglong2*)&sVEt[ii - j + 55][c4 * 4];
        f2fma(a01, ee, v2.x);
        f2fma(a23, ee, v2.y);
        f2fma(e01, ee, ve2.x);
        f2fma(e23, ee, ve2.y);
    }
    float inv = sInv[ii];
    float2 ua = f2unpack(a01), ub = f2unpack(a23);
    float2 uc = f2unpack(e01), ud = f2unpack(e23);
    float vals[8];
    vals[0] = ua.x * inv; vals[1] = uc.x * inv;
    vals[2] = ua.y * inv; vals[3] = uc.y * inv;
    vals[4] = ub.x * inv; vals[5] = ud.x * inv;
    vals[6] = ub.y * inv; vals[7] = ud.y * inv;
    float* ob = so + (size_t)b * (QC * HH) + (g * 32) * HH + ii;
#pragma unroll
    for (int z = 0; z < 4; z++) {
        int c = c4 * 4 + z;
        ob[(2 * c) * HH] = vals[z * 2 + 0];
        ob[(2 * c + 1) * HH] = vals[z * 2 + 1];
    }
    __syncthreads();
    {
        float* sRed = &sSim[0][0];
#pragma unroll
        for (int z = 0; z < 4; z++) {
            sRed[t * 8 + z * 2 + 0] = vals[z * 2 + 0];
            sRed[t * 8 + z * 2 + 1] = vals[z * 2 + 1];
        }
        __syncthreads();
        if (t < 32) {
            int c4r = t >> 3, z = (t >> 1) & 3, p = t & 1;
            int off = z * 2 + p;
            float a1 = 0.f, a2 = 0.f;
            for (int ii2 = 0; ii2 < 56; ii2++) {
                float v = sRed[(c4r * 56 + ii2) * 8 + off];
                a1 += v; a2 = fmaf(v, v, a2);
            }
            atomicAdd(&statOut[2 * (g * 32 + t)], a1);
            atomicAdd(&statOut[2 * (g * 32 + t) + 1], a2);
        }
    }
}

// ---------------- bn_out apply + pair sum, standard layout (prox=1 out) -----
__global__ __launch_bounds__(256) void k_recombine(const float* __restrict__ so,
                                                   float* __restrict__ dst,
                                                   const float* __restrict__ st,
                                                   const float* __restrict__ bog,
                                                   const float* __restrict__ bob) {
    int idx = blockIdx.x * 256 + threadIdx.x;
    if (idx >= NB * CH * HH) return;
    int h = idx % HH;
    int cc = (idx / HH) % CH;
    int row = idx / (HH * CH);
    int o = 2 * cc;
    float m0 = st[2 * o] * INV25088;
    float v0 = st[2 * o + 1] * INV25088 - m0 * m0;
    float a0 = bog[o] * rsqrtf(v0 + 1e-5f);
    float b0 = bob[o] - m0 * a0;
    float m1 = st[2 * o + 2] * INV25088;
    float v1 = st[2 * o + 3] * INV25088 - m1 * m1;
    float a1 = bog[o + 1] * rsqrtf(v1 + 1e-5f);
    float b1 = bob[o + 1] - m1 * a1;
    float v = fmaf(so[(size_t)row * (QC * HH) + o * HH + h], a0, b0) +
              fmaf(so[(size_t)row * (QC * HH) + (o + 1) * HH + h], a1, b1);
    int n = row / HH, wpos = row % HH;
    dst[((size_t)(n * CH + cc) * HH + wpos) * HH + h] = v;
}

// ---------------- bn_out apply + pair sum, TRANSPOSED write (smem tile) -----
// Writes dst[n][c][h][w] = value(w,h), making the next consumer's gather contiguous.
__global__ __launch_bounds__(256) void k_recombine_t(const float* __restrict__ so,
                                                     float* __restrict__ dst,
                                                     const float* __restrict__ st,
                                                     const float* __restrict__ bog,
                                                     const float* __restrict__ bob) {
    __shared__ float sT[56][57];
    int cc = blockIdx.x & 127;
    int n = blockIdx.x >> 7;
    int t = threadIdx.x;
    int o = 2 * cc;
    float m0 = st[2 * o] * INV25088;
    float v0 = st[2 * o + 1] * INV25088 - m0 * m0;
    float a0 = bog[o] * rsqrtf(v0 + 1e-5f);
    float b0 = bob[o] - m0 * a0;
    float m1 = st[2 * o + 2] * INV25088;
    float v1 = st[2 * o + 3] * INV25088 - m1 * m1;
    float a1 = bog[o + 1] * rsqrtf(v1 + 1e-5f);
    float b1 = bob[o + 1] - m1 * a1;
    const float* base = so + ((size_t)n * HH) * (QC * HH);
    for (int i = t; i < 56 * 56; i += 256) {
        int w = i / 56, h = i - w * 56;
        const float* r = base + (size_t)w * (QC * HH) + o * HH + h;
        sT[w][h] = fmaf(r[0], a0, b0) + fmaf(r[HH], a1, b1);
    }
    __syncthreads();
    float* d = dst + ((size_t)(n * CH + cc)) * LTOT;
    for (int i = t; i < 56 * 56; i += 256) {
        int a = i / 56, bb = i - a * 56;
        d[i] = sT[bb][a];
    }
}

// ---------------- grouped conv up + fused bn2 stats -----------------------
__global__ __launch_bounds__(224) void k_conv_up(const float* __restrict__ hbuf,
                                                 const float* __restrict__ w,
                                                 float* __restrict__ out,
                                                 float* __restrict__ statOut) {
    __shared__ float sW[32][16];
    __shared__ float sRs[7][32], sRq[7][32];
    int lt = blockIdx.x % 14;
    int g  = (blockIdx.x / 14) % GG;
    int n  = blockIdx.x / (14 * GG);
    int t = threadIdx.x;
    for (int i = t; i < 512; i += 224) sW[i >> 4][i & 15] = w[(g * 32) * 16 + i];
    __syncthreads();
    int l = lt * 224 + t;
    float acc[32];
#pragma unroll
    for (int o = 0; o < 32; o++) acc[o] = 0.f;
    const float* hp = hbuf + ((size_t)(n * CH + g * 16)) * LTOT + l;
#pragma unroll 4
    for (int k = 0; k < 16; k++) {
        float hv = fmaxf(hp[(size_t)k * LTOT], 0.f);
#pragma unroll
        for (int o = 0; o < 32; o++) acc[o] = fmaf(sW[o][k], hv, acc[o]);
    }
    float* op = out + ((size_t)(n * CIN + g * 32)) * LTOT + l;
#pragma unroll
    for (int o = 0; o < 32; o++) op[(size_t)o * LTOT] = acc[o];
    int lane = t & 31, wp = t >> 5;
#pragma unroll
    for (int o = 0; o < 32; o++) {
        float v = acc[o], v2 = v * v;
#pragma unroll
        for (int off = 16; off; off >>= 1) {
            v += __shfl_xor_sync(~0u, v, off);
            v2 += __shfl_xor_sync(~0u, v2, off);
        }
        if (lane == 0) { sRs[wp][o] = v; sRq[wp][o] = v2; }
    }
    __syncthreads();
    if (t < 32) {
        float a1 = 0.f, a2 = 0.f;
#pragma unroll
        for (int w2 = 0; w2 < 7; w2++) { a1 += sRs[w2][t]; a2 += sRq[w2][t]; }
        atomicAdd(&statOut[(g * 32 + t) * 2], a1);
        atomicAdd(&statOut[(g * 32 + t) * 2 + 1], a2);
    }
}

// ---------------- final: relu(x + bn2(conv_up) * rw), float4, inline coef ----
__global__ __launch_bounds__(256) void k_final(const float4* __restrict__ x,
                                               const float4* __restrict__ cu,
                                               const float* __restrict__ rw,
                                               float4* __restrict__ out,
                                               const float* __restrict__ st,
                                               const float* __restrict__ g2,
                                               const float* __restrict__ b2) {
    int idx = blockIdx.x * 256 + threadIdx.x;
    if (idx >= NN * CIN * (LTOT / 4)) return;
    int ch = (idx / (LTOT / 4)) & 255;
    float m = st[2 * ch] * INV25088;
    float var = st[2 * ch + 1] * INV25088 - m * m;
    float a = g2[ch] * rsqrtf(var + 1e-5f);
    float bb = b2[ch] - m * a;
    float wv = __ldg(rw);
    float4 c = cu[idx], xx = x[idx], r;
    r.x = fmaxf(fmaf(fmaf(c.x, a, bb), wv, xx.x), 0.f);
    r.y = fmaxf(fmaf(fmaf(c.y, a, bb), wv, xx.y), 0.f);
    r.z = fmaxf(fmaf(fmaf(c.z, a, bb), wv, xx.z), 0.f);
    r.w = fmaxf(fmaf(fmaf(c.w, a, bb), wv, xx.w), 0.f);
    out[idx] = r;
}

// ---------------- launch ----------------
extern "C" void kernel_launch(void* const* d_in, const int* in_sizes, int n_in,
                              void* d_out, int out_size) {
    const float* x    = (const float*)d_in[0];
    const float* cdw  = (const float*)d_in[1];
    const float* bn1g = (const float*)d_in[2];
    const float* bn1b = (const float*)d_in[3];
    const float* qkvw = (const float*)d_in[4];
    const float* bqg  = (const float*)d_in[5];
    const float* bqb  = (const float*)d_in[6];
    const float* bsg  = (const float*)d_in[7];
    const float* bsb  = (const float*)d_in[8];
    const float* bog  = (const float*)d_in[9];
    const float* bob  = (const float*)d_in[10];
    const float* rel  = (const float*)d_in[11];
    const float* cuw  = (const float*)d_in[12];
    const float* bn2g = (const float*)d_in[13];
    const float* bn2b = (const float*)d_in[14];
    const float* rw   = (const float*)d_in[15];
    float* out = (float*)d_out;

    float *fA, *fB, *qk, *so, *gs;
    cudaGetSymbolAddress((void**)&fA, g_featA);
    cudaGetSymbolAddress((void**)&fB, g_featB);
    cudaGetSymbolAddress((void**)&qk, g_qkv);
    cudaGetSymbolAddress((void**)&so, g_so);
    cudaGetSymbolAddress((void**)&gs, g_stats);

    k_init<<<28, 256>>>(rel);
    k_conv_down<<<896, 224>>>(x, cdw, fA, gs + OFF_BN1);

    // axial 0: src fA (standard), out fB TRANSPOSED (via k_recombine_t)
    // axial 1: src fB (transposed → contiguous gather), out fA (k_recombine_t = correct prox=0 layout)
    // axial 2: src fA (standard), out fB standard (k_recombine)
    const float* srcs[3] = {fA, fB, fA};
    float* dsts[3]       = {fB, fA, fB};
    for (int i = 0; i < 3; i++) {
        float* bnqSt = gs + OFF_BNQ + i * 512;
        float* simSt = gs + OFF_SIM + i * 384;
        float* bnoSt = gs + OFF_BNO + i * 512;
        if (i == 0)
            k_qkv<1><<<448, 256>>>(srcs[i], qkvw + i * QC * CH, qk, gs + OFF_BN1, bn1g, bn1b, bnqSt);
        else
            k_qkv<0><<<448, 256>>>(srcs[i], qkvw + i * QC * CH, qk, gs, bn1g, bn1b, bnqSt);
        k_simstats2<<<448, 256>>>(qk, i, bnqSt, bqg + i * 256, bqb + i * 256, simSt);
        k_attn<<<3584, 224>>>(qk, rel + i * 32 * RELW, so,
                              bnqSt, bqg + i * 256, bqb + i * 256,
                              simSt, bsg + i * 24, bsb + i * 24, bnoSt);
        if (i == 2) k_recombine<<<12544, 256>>>(so, dsts[i], bnoSt, bog + i * 256, bob + i * 256);
        else        k_recombine_t<<<1024, 256>>>(so, dsts[i], bnoSt, bog + i * 256, bob + i * 256);
    }

    k_conv_up<<<896, 224>>>(fB, cuw, qk, gs + OFF_BN2);
    k_final<<<6272, 256>>>((const float4*)x, (const float4*)qk, rw, (float4*)out,
                           gs + OFF_BN2, bn2g, bn2b);
}

// round 16
// speedup vs baseline: 1.0217x; 1.0027x over previous
#include <cuda_runtime.h>

#define NN 8
#define CIN 256
#define LTOT 3136
#define CH 128
#define GG 8
#define HH 56
#define NB 448          // NN*56
#define QC 256
#define RELW 111
#define INV25088 (1.f / 25088.f)

// ---------------- device scratch (static, no allocation) ----------------
__device__ float g_featA[NN * CH * LTOT];   // 12.8 MB
__device__ float g_featB[NN * CH * LTOT];   // 12.8 MB
__device__ float g_qkv[NB * QC * HH];       // 25.7 MB (reused for conv_up out)
__device__ float g_so[NB * QC * HH];        // 25.7 MB
__device__ float g_stats[4992];             // all BN stat accumulators (see offsets)
__device__ float g_SU[3][2][8][56];         // sliding sums of rel_q / rel_k per axial
__device__ float g_U[3][2][56][64];         // sliding pair-product sums, i-MAJOR
__device__ float2 g_E2[3][8][112];          // packed (QE[c][d], KE[c][110-d])
__device__ float g_VE2[3][112][16];         // VE transposed [d][c]

// offsets into g_stats
#define OFF_BN1 0            // 2*128
#define OFF_BNQ 256          // 3 * 512
#define OFF_SIM 1792         // 3 * 8 replicas * 48
#define OFF_BNO 2944         // 3 * 512
#define OFF_BN2 4480         // 2*256
#define STATS_TOTAL 4992

#define QKV_DSMEM ((7296 + 2 * 256 * 12) * 4)   // sX + 2 weight buffers = 53760 B

// ---------------- helpers ----------------
__device__ __forceinline__ float fast_exp(float x) {
    float y = x * 1.4426950408889634f;
    y = fmaxf(y, -120.0f);
    float n = floorf(y);
    float f = y - n;
    float p = 1.8775767e-3f;
    p = fmaf(p, f, 8.9893397e-3f);
    p = fmaf(p, f, 5.5826318e-2f);
    p = fmaf(p, f, 2.4015361e-1f);
    p = fmaf(p, f, 6.9315308e-1f);
    p = fmaf(p, f, 9.9999994e-1f);
    return p * __int_as_float(((int)n + 127) << 23);
}

// packed f32x2 ops (Blackwell FFMA2 — PTX-only pattern)
__device__ __forceinline__ unsigned long long f2pack(float lo, float hi) {
    unsigned long long r;
    asm("mov.b64 %0, {%1, %2};" : "=l"(r) : "f"(lo), "f"(hi));
    return r;
}
__device__ __forceinline__ void f2fma(unsigned long long& d, unsigned long long a,
                                      unsigned long long b) {
    asm("fma.rn.f32x2 %0, %1, %2, %0;" : "+l"(d) : "l"(a), "l"(b));
}
__device__ __forceinline__ float2 f2unpack(unsigned long long v) {
    float2 r;
    asm("mov.b64 {%0, %1}, %2;" : "=f"(r.x), "=f"(r.y) : "l"(v));
    return r;
}

// ---------------- init: rel tables (all 3 axials) + packed attn tables + zero stats
__global__ void k_init(const float* __restrict__ rel) {
    int bid = blockIdx.x;
    int t = threadIdx.x;
    if (bid < 24) {
        int a = bid >> 3;
        const float* rb = rel + a * 32 * RELW;
        int w = (bid & 7) * 256 + t;   // 0..2047
#pragma unroll
        for (int rep = 0; rep < 4; rep++, w += 2048) {
            if (w < 7168) {
                int s = w / 3584;
                int r = w - s * 3584;
                int P = r / 56, i = r % 56;
                int c = P >> 3, cp = P & 7;
                const float* r1 = rb + (s * 8 + c) * RELW + i;
                const float* r2 = rb + (s * 8 + cp) * RELW + i;
                float u = 0.f;
#pragma unroll
                for (int d = 0; d < 56; d++) u = fmaf(r1[d], r2[d], u);
                g_U[a][s][i][P] = u;
            } else if (w < 8064) {
                int w2 = w - 7168;
                int s = w2 / 448;
                int r = w2 - s * 448;
                int c = r / 56, i = r % 56;
                const float* rr = rb + (s * 8 + c) * RELW + i;
                float u = 0.f;
#pragma unroll
                for (int d = 0; d < 56; d++) u += rr[d];
                g_SU[a][s][c][i] = u;
            }
        }
    } else if (bid < 28) {
        for (int i = (bid - 24) * 256 + t; i < STATS_TOTAL; i += 4 * 256)
            g_stats[i] = 0.f;
    } else {
        int idx = bid - 28;          // 0..5
        int a = idx >> 1, half = idx & 1;
        const float* rb = rel + a * 32 * RELW;
        if (half == 0) {
            for (int i = t; i < 8 * 111; i += 256) {
                int c = i / 111, d = i - c * 111;
                g_E2[a][c][d] = make_float2(rb[c * RELW + d], rb[(8 + c) * RELW + (110 - d)]);
            }
        } else {
            for (int i = t; i < 16 * 111; i += 256) {
                int c = i / 111, d = i - c * 111;
                g_VE2[a][d][c] = rb[(16 + c) * RELW + d];
            }
        }
    }
}

// ---------------- grouped conv down + fused bn1 stats ----------------
__global__ __launch_bounds__(224) void k_conv_down(const float* __restrict__ x,
                                                   const float* __restrict__ w,
                                                   float* __restrict__ out,
                                                   float* __restrict__ statOut) {
    __shared__ float sW[16][32];
    __shared__ float sRs[7][16], sRq[7][16];
    int lt = blockIdx.x % 14;
    int g  = (blockIdx.x / 14) % GG;
    int n  = blockIdx.x / (14 * GG);
    int t = threadIdx.x;
    for (int i = t; i < 512; i += 224) sW[i >> 5][i & 31] = w[(g * 16) * 32 + i];
    __syncthreads();
    int l = lt * 224 + t;
    float acc[16];
#pragma unroll
    for (int o = 0; o < 16; o++) acc[o] = 0.f;
    const float* xp = x + ((size_t)(n * CIN + g * 32)) * LTOT + l;
#pragma unroll 8
    for (int k = 0; k < 32; k++) {
        float xv = xp[(size_t)k * LTOT];
#pragma unroll
        for (int o = 0; o < 16; o++) acc[o] = fmaf(sW[o][k], xv, acc[o]);
    }
    float* op = out + ((size_t)(n * CH + g * 16)) * LTOT + l;
#pragma unroll
    for (int o = 0; o < 16; o++) op[(size_t)o * LTOT] = acc[o];
    int lane = t & 31, wp = t >> 5;
#pragma unroll
    for (int o = 0; o < 16; o++) {
        float v = acc[o], v2 = v * v;
#pragma unroll
        for (int off = 16; off; off >>= 1) {
            v += __shfl_xor_sync(~0u, v, off);
            v2 += __shfl_xor_sync(~0u, v2, off);
        }
        if (lane == 0) { sRs[wp][o] = v; sRq[wp][o] = v2; }
    }
    __syncthreads();
    if (t < 16) {
        float a1 = 0.f, a2 = 0.f;
#pragma unroll
        for (int w2 = 0; w2 < 7; w2++) { a1 += sRs[w2][t]; a2 += sRq[w2][t]; }
        atomicAdd(&statOut[(g * 16 + t) * 2], a1);
        atomicAdd(&statOut[(g * 16 + t) * 2 + 1], a2);
    }
}

// ---------------- QKV GEMM: double-buffered weights, dynamic smem -----------
template <int USEBN>
__global__ __launch_bounds__(256, 2) void k_qkv(const float* __restrict__ src,
                                                const float* __restrict__ W,
                                                float* __restrict__ qkv,
                                                const float* __restrict__ inStat,
                                                const float* __restrict__ gam,
                                                const float* __restrict__ bet,
                                                float* __restrict__ statOut) {
    extern __shared__ float dyn[];
    float* sX = dyn;                                   // [128][57] = 7296 floats
    float (*sWb)[12] = (float(*)[12])(dyn + 7296);     // [2*256][12]
    int b = blockIdx.x;
    int n = b / HH, wpos = b % HH;
    int t = threadIdx.x;
    // coefs in buffer 1 (untouched until first STS phase, which is after a sync)
    float* sCA = &sWb[256][0];
    float* sCB = sCA + 128;
    if (USEBN) {
        if (t < 128) {
            float m = inStat[2 * t] * INV25088;
            float var = inStat[2 * t + 1] * INV25088 - m * m;
            float a = gam[t] * rsqrtf(var + 1e-5f);
            sCA[t] = a; sCB[t] = bet[t] - m * a;
        }
        __syncthreads();
    }
    for (int i = t; i < CH * HH; i += 256) {
        int c = i / HH, h = i - c * HH;
        float v = src[((size_t)(n * CH + c) * HH + wpos) * HH + h];
        if (USEBN) { v = fmaf(v, sCA[c], sCB[c]); v = fmaxf(v, 0.f); }
        sX[c * 57 + h] = v;
    }
    // preload weight chunk 0 into buffer 0
    for (int i = t; i < 2048; i += 256)
        sWb[i >> 3][i & 7] = W[(i >> 3) * 128 + (i & 7)];
    __syncthreads();

    int o0 = t & 31;
    int h0 = (t >> 5) * 7;
    unsigned long long acc01[8], acc23[8], acc45[8];
    float acc6[8];
#pragma unroll
    for (int m = 0; m < 8; m++) {
        acc01[m] = 0ull; acc23[m] = 0ull; acc45[m] = 0ull; acc6[m] = 0.f;
    }

    int cur = 0;
    for (int ci = 0; ci < 16; ci++) {
        int cc = ci * 8;
        float pre[8];
        if (ci < 15) {
#pragma unroll
            for (int r = 0; r < 8; r++) {
                int i = t + 256 * r;
                pre[r] = W[(i >> 3) * 128 + (cc + 8) + (i & 7)];
            }
        }
        float (*sWc)[12] = sWb + cur * 256;
#pragma unroll
        for (int j4 = 0; j4 < 2; j4++) {
            float4 w4[8];
#pragma unroll
            for (int m = 0; m < 8; m++)
                w4[m] = *(const float4*)&sWc[o0 + 32 * m][j4 * 4];
#pragma unroll
            for (int jj = 0; jj < 4; jj++) {
                int c = cc + j4 * 4 + jj;
                float xv[7];
#pragma unroll
                for (int u = 0; u < 7; u++) xv[u] = sX[c * 57 + h0 + u];
                unsigned long long x01 = f2pack(xv[0], xv[1]);
                unsigned long long x23 = f2pack(xv[2], xv[3]);
                unsigned long long x45 = f2pack(xv[4], xv[5]);
#pragma unroll
                for (int m = 0; m < 8; m++) {
                    float wv = (jj == 0) ? w4[m].x : (jj == 1) ? w4[m].y
                             : (jj == 2) ? w4[m].z : w4[m].w;
                    unsigned long long w2 = f2pack(wv, wv);
                    f2fma(acc01[m], w2, x01);
                    f2fma(acc23[m], w2, x23);
                    f2fma(acc45[m], w2, x45);
                    acc6[m] = fmaf(wv, xv[6], acc6[m]);
                }
            }
        }
        if (ci < 15) {
            float (*sWn)[12] = sWb + (1 - cur) * 256;
#pragma unroll
            for (int r = 0; r < 8; r++) {
                int i = t + 256 * r;
                sWn[i >> 3][i & 7] = pre[r];
            }
        }
        __syncthreads();
        cur ^= 1;
    }
    // unpack accumulators
    float acc[8][7];
#pragma unroll
    for (int m = 0; m < 8; m++) {
        float2 a0 = f2unpack(acc01[m]);
        float2 a1 = f2unpack(acc23[m]);
        float2 a2 = f2unpack(acc45[m]);
        acc[m][0] = a0.x; acc[m][1] = a0.y;
        acc[m][2] = a1.x; acc[m][3] = a1.y;
        acc[m][4] = a2.x; acc[m][5] = a2.y;
        acc[m][6] = acc6[m];
    }
    // ---- fused stats (scratch = sX region) ----
    {
        float* scr = sX;
        int wp = t >> 5;
#pragma unroll
        for (int m = 0; m < 8; m++) {
            float s = 0.f, qq = 0.f;
#pragma unroll
            for (int u = 0; u < 7; u++) { float v = acc[m][u]; s += v; qq = fmaf(v, v, qq); }
            scr[wp * 256 + o0 + 32 * m] = s;
            scr[2048 + wp * 256 + o0 + 32 * m] = qq;
        }
        __syncthreads();
        float a1 = 0.f, a2 = 0.f;
#pragma unroll
        for (int w2 = 0; w2 < 8; w2++) {
            a1 += scr[w2 * 256 + t];
            a2 += scr[2048 + w2 * 256 + t];
        }
        atomicAdd(&statOut[2 * t], a1);
        atomicAdd(&statOut[2 * t + 1], a2);
    }
    // ---- stage output through smem for coalesced global writes ----
    float* sOut = sX;
#pragma unroll
    for (int half = 0; half < 2; half++) {
        __syncthreads();
#pragma unroll
        for (int m = 0; m < 4; m++) {
            int mm = m + 4 * half;
            int orow = o0 + 32 * m;
#pragma unroll
            for (int u = 0; u < 7; u++) sOut[orow * 57 + h0 + u] = acc[mm][u];
        }
        __syncthreads();
        float* dst = qkv + (size_t)b * (QC * HH) + half * 128 * HH;
        for (int i = t; i < 128 * HH; i += 256) {
            int o = i / HH, h = i - o * HH;
            dst[i] = sOut[o * 57 + h];
        }
    }
}

// ---------------- algebraic sim BN stats + inline bnq coef ------------------
__global__ __launch_bounds__(256, 4) void k_simstats2(const float* __restrict__ qkv, int axial,
                                                      const float* __restrict__ bnqStat,
                                                      const float* __restrict__ gam,
                                                      const float* __restrict__ bet,
                                                      float* __restrict__ simOut) {
    __shared__ float sD[128][57];
    __shared__ float sCA[256], sCB[256];
    int b = blockIdx.x;
    int t = threadIdx.x;
    {
        float m = bnqStat[2 * t] * INV25088;
        float var = bnqStat[2 * t + 1] * INV25088 - m * m;
        float a = gam[t] * rsqrtf(var + 1e-5f);
        sCA[t] = a; sCB[t] = bet[t] - m * a;
    }
    __syncthreads();
    const float* base = qkv + (size_t)b * (QC * HH);
    for (int i = t; i < 128 * HH; i += 256) {
        int lc = i / HH, h = i - lc * HH;
        int g = lc >> 4, c = lc & 15;
        int o = g * 32 + c;
        sD[lc][h] = fmaf(base[o * HH + h], sCA[o], sCB[o]);
    }
    __syncthreads();
    int g = t >> 5, lane = t & 31;
    float accG[4], accW[4];
#pragma unroll
    for (int jj = 0; jj < 4; jj++) {
        int s = jj >> 1;
        int P = lane + 32 * (jj & 1);
        int c = P >> 3, cp = P & 7;
        const float* x1 = &sD[g * 16 + s * 8 + c][0];
        const float* x2 = &sD[g * 16 + s * 8 + cp][0];
        const float* U = &g_U[axial][s][0][P];
        float gg = 0.f, ww = 0.f;
#pragma unroll
        for (int i = 0; i < 56; i++) {
            float p = x1[i] * x2[i];
            gg += p;
            ww = fmaf(p, __ldg(U + i * 64), ww);
        }
        accG[jj] = gg; accW[jj] = ww;
    }
    float pqk = 0.f, pqr = 0.f, pkr = 0.f;
    if (lane < 8) {
        const float* xq = &sD[g * 16 + lane][0];
        const float* xk = &sD[g * 16 + 8 + lane][0];
        float sq = 0.f, sk = 0.f, vq = 0.f, vk = 0.f;
#pragma unroll
        for (int i = 0; i < 56; i++) {
            sq += xq[i]; sk += xk[i];
            vq = fmaf(xq[i], __ldg(&g_SU[axial][0][lane][i]), vq);
            vk = fmaf(xk[i], __ldg(&g_SU[axial][1][lane][i]), vk);
        }
        pqk = sq * sk; pqr = vq; pkr = vk;
    }
    float ssqk = accG[0] * accG[2] + accG[1] * accG[3];
    float ssqr = accW[0] + accW[1];
    float sskr = accW[2] + accW[3];
#pragma unroll
    for (int off = 16; off; off >>= 1) {
        pqk += __shfl_xor_sync(~0u, pqk, off);
        pqr += __shfl_xor_sync(~0u, pqr, off);
        pkr += __shfl_xor_sync(~0u, pkr, off);
        ssqk += __shfl_xor_sync(~0u, ssqk, off);
        ssqr += __shfl_xor_sync(~0u, ssqr, off);
        sskr += __shfl_xor_sync(~0u, sskr, off);
    }
    if (lane == 0) {
        float* st = simOut + (b & 7) * 48;
        atomicAdd(&st[(0 * 8 + g) * 2 + 0], pqk);
        atomicAdd(&st[(0 * 8 + g) * 2 + 1], ssqk);
        atomicAdd(&st[(1 * 8 + g) * 2 + 0], pqr);
        atomicAdd(&st[(1 * 8 + g) * 2 + 1], ssqr);
        atomicAdd(&st[(2 * 8 + g) * 2 + 0], pkr);
        atomicAdd(&st[(2 * 8 + g) * 2 + 1], sskr);
    }
}

// ---------------- fused attention (precomputed packed tables) ---------------
__global__ __launch_bounds__(224) void k_attn(const float* __restrict__ qkv, int axial,
                                              float* __restrict__ so,
                                              const float* __restrict__ bnqStat,
                                              const float* __restrict__ bqg,
                                              const float* __restrict__ bqb,
                                              const float* __restrict__ simStat,
                                              const float* __restrict__ bsg,
                                              const float* __restrict__ bsb,
                                              float* __restrict__ statOut) {
    __shared__ float sQ[8][57], sK[8][57];
    __shared__ __align__(16) float sVt[56][20];     // [h][c], pad 20
    __shared__ float2 sE2[8][112];                  // packed (QE, KE-rev)
    __shared__ __align__(16) float sVEt[112][20];   // [d][c], pad 20
    __shared__ float sSim[56][57];
    __shared__ float sInv[56];
    __shared__ float sCA[32], sCB[32], sP[6];
    int g = blockIdx.x & 7;
    int b = blockIdx.x >> 3;
    int t = threadIdx.x;
    if (t < 32) {
        int o = g * 32 + t;
        float m = bnqStat[2 * o] * INV25088;
        float var = bnqStat[2 * o + 1] * INV25088 - m * m;
        float a = bqg[o] * rsqrtf(var + 1e-5f);
        sCA[t] = a; sCB[t] = bqb[o] - m * a;
    } else if (t < 35) {
        int p = t - 32;
        int ch = p * 8 + g;
        float s1 = 0.f, s2 = 0.f;
#pragma unroll
        for (int r = 0; r < 8; r++) { s1 += simStat[r * 48 + ch * 2]; s2 += simStat[r * 48 + ch * 2 + 1]; }
        const float invc = 1.f / (448.f * 3136.f);
        float m = s1 * invc;
        float var = s2 * invc - m * m;
        float a = bsg[ch] * rsqrtf(var + 1e-5f);
        sP[p] = a; sP[3 + p] = bsb[ch] - m * a;
    }
    __syncthreads();
    const float* base = qkv + (size_t)b * (QC * HH) + g * 32 * HH;
    for (int i = t; i < 32 * HH; i += 224) {
        int c = i / HH, h = i - c * HH;
        float v = fmaf(base[c * HH + h], sCA[c], sCB[c]);
        if (c < 8) sQ[c][h] = v;
        else if (c < 16) sK[c - 8][h] = v;
        else sVt[h][c - 16] = v;
    }
    {
        const float2* e2src = &g_E2[axial][0][0];
        float2* e2dst = &sE2[0][0];
        for (int i = t; i < 8 * 112; i += 224) e2dst[i] = __ldg(e2src + i);
        const float* vsrc = &g_VE2[axial][0][0];
        for (int i = t; i < 112 * 16; i += 224) sVEt[i >> 4][i & 15] = __ldg(vsrc + i);
    }
    __syncthreads();
    float aqk = sP[0], aqr = sP[1], akr = sP[2];
    float bias = sP[3] + sP[4] + sP[5];
    int i0 = t >> 2, jt = t & 3;
    float qv[8];
#pragma unroll
    for (int c = 0; c < 8; c++) qv[c] = sQ[c][i0];
    float lg[14];
#pragma unroll
    for (int u = 0; u < 14; u++) {
        int j = jt * 14 + u;
        int d1 = i0 - j + 55;
        float qk = 0.f, qr = 0.f, kr = 0.f;
#pragma unroll
        for (int c = 0; c < 8; c++) {
            float kj = sK[c][j];
            float2 e2 = sE2[c][d1];
            qk = fmaf(qv[c], kj, qk);
            qr = fmaf(qv[c], e2.x, qr);
            kr = fmaf(kj, e2.y, kr);
        }
        lg[u] = fmaf(aqk, qk, fmaf(aqr, qr, fmaf(akr, kr, bias)));
    }
    float m = -1e30f;
#pragma unroll
    for (int u = 0; u < 14; u++) m = fmaxf(m, lg[u]);
    m = fmaxf(m, __shfl_xor_sync(~0u, m, 1));
    m = fmaxf(m, __shfl_xor_sync(~0u, m, 2));
    float s = 0.f;
#pragma unroll
    for (int u = 0; u < 14; u++) { lg[u] = fast_exp(lg[u] - m); s += lg[u]; }
    s += __shfl_xor_sync(~0u, s, 1);
    s += __shfl_xor_sync(~0u, s, 2);
#pragma unroll
    for (int u = 0; u < 14; u++) sSim[i0][jt * 14 + u] = lg[u];
    if (jt == 0) sInv[i0] = 1.f / s;
    __syncthreads();
    int c4 = t / 56, ii = t % 56;
    unsigned long long a01 = 0ull, a23 = 0ull, e01 = 0ull, e23 = 0ull;
#pragma unroll 4
    for (int j = 0; j < 56; j++) {
        float e = sSim[ii][j];
        unsigned long long ee = f2pack(e, e);
        ulonglong2 v2 = *(const ulonglong2*)&sVt[j][c4 * 4];
        ulonglong2 ve2 = *(const ulonglong2*)&sVEt[ii - j + 55][c4 * 4];
        f2fma(a01, ee, v2.x);
        f2fma(a23, ee, v2.y);
        f2fma(e01, ee, ve2.x);
        f2fma(e23, ee, ve2.y);
    }
    float inv = sInv[ii];
    float2 ua = f2unpack(a01), ub = f2unpack(a23);
    float2 uc = f2unpack(e01), ud = f2unpack(e23);
    float vals[8];
    vals[0] = ua.x * inv; vals[1] = uc.x * inv;
    vals[2] = ua.y * inv; vals[3] = uc.y * inv;
    vals[4] = ub.x * inv; vals[5] = ud.x * inv;
    vals[6] = ub.y * inv; vals[7] = ud.y * inv;
    float* ob = so + (size_t)b * (QC * HH) + (g * 32) * HH + ii;
#pragma unroll
    for (int z = 0; z < 4; z++) {
        int c = c4 * 4 + z;
        ob[(2 * c) * HH] = vals[z * 2 + 0];
        ob[(2 * c + 1) * HH] = vals[z * 2 + 1];
    }
    __syncthreads();
    {
        float* sRed = &sSim[0][0];
#pragma unroll
        for (int z = 0; z < 4; z++) {
            sRed[t * 8 + z * 2 + 0] = vals[z * 2 + 0];
            sRed[t * 8 + z * 2 + 1] = vals[z * 2 + 1];
        }
        __syncthreads();
        if (t < 32) {
            int c4r = t >> 3, z = (t >> 1) & 3, p = t & 1;
            int off = z * 2 + p;
            float a1 = 0.f, a2 = 0.f;
            for (int ii2 = 0; ii2 < 56; ii2++) {
                float v = sRed[(c4r * 56 + ii2) * 8 + off];
                a1 += v; a2 = fmaf(v, v, a2);
            }
            atomicAdd(&statOut[2 * (g * 32 + t)], a1);
            atomicAdd(&statOut[2 * (g * 32 + t) + 1], a2);
        }
    }
}

// ---------------- bn_out apply + pair sum, standard layout ------------------
__global__ __launch_bounds__(256) void k_recombine(const float* __restrict__ so,
                                                   float* __restrict__ dst,
                                                   const float* __restrict__ st,
                                                   const float* __restrict__ bog,
                                                   const float* __restrict__ bob) {
    int idx = blockIdx.x * 256 + threadIdx.x;
    if (idx >= NB * CH * HH) return;
    int h = idx % HH;
    int cc = (idx / HH) % CH;
    int row = idx / (HH * CH);
    int o = 2 * cc;
    float m0 = st[2 * o] * INV25088;
    float v0 = st[2 * o + 1] * INV25088 - m0 * m0;
    float a0 = bog[o] * rsqrtf(v0 + 1e-5f);
    float b0 = bob[o] - m0 * a0;
    float m1 = st[2 * o + 2] * INV25088;
    float v1 = st[2 * o + 3] * INV25088 - m1 * m1;
    float a1 = bog[o + 1] * rsqrtf(v1 + 1e-5f);
    float b1 = bob[o + 1] - m1 * a1;
    float v = fmaf(so[(size_t)row * (QC * HH) + o * HH + h], a0, b0) +
              fmaf(so[(size_t)row * (QC * HH) + (o + 1) * HH + h], a1, b1);
    int n = row / HH, wpos = row % HH;
    dst[((size_t)(n * CH + cc) * HH + wpos) * HH + h] = v;
}

// ---------------- bn_out apply + pair sum, TRANSPOSED write -----------------
__global__ __launch_bounds__(256) void k_recombine_t(const float* __restrict__ so,
                                                     float* __restrict__ dst,
                                                     const float* __restrict__ st,
                                                     const float* __restrict__ bog,
                                                     const float* __restrict__ bob) {
    __shared__ float sT[56][57];
    int cc = blockIdx.x & 127;
    int n = blockIdx.x >> 7;
    int t = threadIdx.x;
    int o = 2 * cc;
    float m0 = st[2 * o] * INV25088;
    float v0 = st[2 * o + 1] * INV25088 - m0 * m0;
    float a0 = bog[o] * rsqrtf(v0 + 1e-5f);
    float b0 = bob[o] - m0 * a0;
    float m1 = st[2 * o + 2] * INV25088;
    float v1 = st[2 * o + 3] * INV25088 - m1 * m1;
    float a1 = bog[o + 1] * rsqrtf(v1 + 1e-5f);
    float b1 = bob[o + 1] - m1 * a1;
    const float* base = so + ((size_t)n * HH) * (QC * HH);
    for (int i = t; i < 56 * 56; i += 256) {
        int w = i / 56, h = i - w * 56;
        const float* r = base + (size_t)w * (QC * HH) + o * HH + h;
        sT[w][h] = fmaf(r[0], a0, b0) + fmaf(r[HH], a1, b1);
    }
    __syncthreads();
    float* d = dst + ((size_t)(n * CH + cc)) * LTOT;
    for (int i = t; i < 56 * 56; i += 256) {
        int a = i / 56, bb = i - a * 56;
        d[i] = sT[bb][a];
    }
}

// ---------------- grouped conv up + fused bn2 stats -----------------------
__global__ __launch_bounds__(224) void k_conv_up(const float* __restrict__ hbuf,
                                                 const float* __restrict__ w,
                                                 float* __restrict__ out,
                                                 float* __restrict__ statOut) {
    __shared__ float sW[32][16];
    __shared__ float sRs[7][32], sRq[7][32];
    int lt = blockIdx.x % 14;
    int g  = (blockIdx.x / 14) % GG;
    int n  = blockIdx.x / (14 * GG);
    int t = threadIdx.x;
    for (int i = t; i < 512; i += 224) sW[i >> 4][i & 15] = w[(g * 32) * 16 + i];
    __syncthreads();
    int l = lt * 224 + t;
    float acc[32];
#pragma unroll
    for (int o = 0; o < 32; o++) acc[o] = 0.f;
    const float* hp = hbuf + ((size_t)(n * CH + g * 16)) * LTOT + l;
#pragma unroll 4
    for (int k = 0; k < 16; k++) {
        float hv = fmaxf(hp[(size_t)k * LTOT], 0.f);
#pragma unroll
        for (int o = 0; o < 32; o++) acc[o] = fmaf(sW[o][k], hv, acc[o]);
    }
    float* op = out + ((size_t)(n * CIN + g * 32)) * LTOT + l;
#pragma unroll
    for (int o = 0; o < 32; o++) op[(size_t)o * LTOT] = acc[o];
    int lane = t & 31, wp = t >> 5;
#pragma unroll
    for (int o = 0; o < 32; o++) {
        float v = acc[o], v2 = v * v;
#pragma unroll
        for (int off = 16; off; off >>= 1) {
            v += __shfl_xor_sync(~0u, v, off);
            v2 += __shfl_xor_sync(~0u, v2, off);
        }
        if (lane == 0) { sRs[wp][o] = v; sRq[wp][o] = v2; }
    }
    __syncthreads();
    if (t < 32) {
        float a1 = 0.f, a2 = 0.f;
#pragma unroll
        for (int w2 = 0; w2 < 7; w2++) { a1 += sRs[w2][t]; a2 += sRq[w2][t]; }
        atomicAdd(&statOut[(g * 32 + t) * 2], a1);
        atomicAdd(&statOut[(g * 32 + t) * 2 + 1], a2);
    }
}

// ---------------- final: relu(x + bn2(conv_up) * rw), float4, inline coef ----
__global__ __launch_bounds__(256) void k_final(const float4* __restrict__ x,
                                               const float4* __restrict__ cu,
                                               const float* __restrict__ rw,
                                               float4* __restrict__ out,
                                               const float* __restrict__ st,
                                               const float* __restrict__ g2,
                                               const float* __restrict__ b2) {
    int idx = blockIdx.x * 256 + threadIdx.x;
    if (idx >= NN * CIN * (LTOT / 4)) return;
    int ch = (idx / (LTOT / 4)) & 255;
    float m = st[2 * ch] * INV25088;
    float var = st[2 * ch + 1] * INV25088 - m * m;
    float a = g2[ch] * rsqrtf(var + 1e-5f);
    float bb = b2[ch] - m * a;
    float wv = __ldg(rw);
    float4 c = cu[idx], xx = x[idx], r;
    r.x = fmaxf(fmaf(fmaf(c.x, a, bb), wv, xx.x), 0.f);
    r.y = fmaxf(fmaf(fmaf(c.y, a, bb), wv, xx.y), 0.f);
    r.z = fmaxf(fmaf(fmaf(c.z, a, bb), wv, xx.z), 0.f);
    r.w = fmaxf(fmaf(fmaf(c.w, a, bb), wv, xx.w), 0.f);
    out[idx] = r;
}

// ---------------- launch ----------------
extern "C" void kernel_launch(void* const* d_in, const int* in_sizes, int n_in,
                              void* d_out, int out_size) {
    const float* x    = (const float*)d_in[0];
    const float* cdw  = (const float*)d_in[1];
    const float* bn1g = (const float*)d_in[2];
    const float* bn1b = (const float*)d_in[3];
    const float* qkvw = (const float*)d_in[4];
    const float* bqg  = (const float*)d_in[5];
    const float* bqb  = (const float*)d_in[6];
    const float* bsg  = (const float*)d_in[7];
    const float* bsb  = (const float*)d_in[8];
    const float* bog  = (const float*)d_in[9];
    const float* bob  = (const float*)d_in[10];
    const float* rel  = (const float*)d_in[11];
    const float* cuw  = (const float*)d_in[12];
    const float* bn2g = (const float*)d_in[13];
    const float* bn2b = (const float*)d_in[14];
    const float* rw   = (const float*)d_in[15];
    float* out = (float*)d_out;

    float *fA, *fB, *qk, *so, *gs;
    cudaGetSymbolAddress((void**)&fA, g_featA);
    cudaGetSymbolAddress((void**)&fB, g_featB);
    cudaGetSymbolAddress((void**)&qk, g_qkv);
    cudaGetSymbolAddress((void**)&so, g_so);
    cudaGetSymbolAddress((void**)&gs, g_stats);

    // opt-in to >48KB dynamic smem for the qkv kernels (host-side, idempotent)
    cudaFuncSetAttribute(k_qkv<1>, cudaFuncAttributeMaxDynamicSharedMemorySize, QKV_DSMEM);
    cudaFuncSetAttribute(k_qkv<0>, cudaFuncAttributeMaxDynamicSharedMemorySize, QKV_DSMEM);

    k_init<<<34, 256>>>(rel);
    k_conv_down<<<896, 224>>>(x, cdw, fA, gs + OFF_BN1);

    // axial 0: src fA (standard), out fB TRANSPOSED (k_recombine_t)
    // axial 1: src fB (transposed -> contiguous gather), out fA (k_recombine_t)
    // axial 2: src fA (standard), out fB standard (k_recombine)
    const float* srcs[3] = {fA, fB, fA};
    float* dsts[3]       = {fB, fA, fB};
    for (int i = 0; i < 3; i++) {
        float* bnqSt = gs + OFF_BNQ + i * 512;
        float* simSt = gs + OFF_SIM + i * 384;
        float* bnoSt = gs + OFF_BNO + i * 512;
        if (i == 0)
            k_qkv<1><<<448, 256, QKV_DSMEM>>>(srcs[i], qkvw + i * QC * CH, qk, gs + OFF_BN1, bn1g, bn1b, bnqSt);
        else
            k_qkv<0><<<448, 256, QKV_DSMEM>>>(srcs[i], qkvw + i * QC * CH, qk, gs, bn1g, bn1b, bnqSt);
        k_simstats2<<<448, 256>>>(qk, i, bnqSt, bqg + i * 256, bqb + i * 256, simSt);
        k_attn<<<3584, 224>>>(qk, i, so,
                              bnqSt, bqg + i * 256, bqb + i * 256,
                              simSt, bsg + i * 24, bsb + i * 24, bnoSt);
        if (i == 2) k_recombine<<<12544, 256>>>(so, dsts[i], bnoSt, bog + i * 256, bob + i * 256);
        else        k_recombine_t<<<1024, 256>>>(so, dsts[i], bnoSt, bog + i * 256, bob + i * 256);
    }

    k_conv_up<<<896, 224>>>(fB, cuw, qk, gs + OFF_BN2);
    k_final<<<6272, 256>>>((const float4*)x, (const float4*)qk, rw, (float4*)out,
                           gs + OFF_BN2, bn2g, bn2b);
}